// round 1
// baseline (speedup 1.0000x reference)
#include <cuda_runtime.h>
#include <cuda_bf16.h>

// Problem constants
#define B_   2
#define T_   128
#define C_   527
#define DA_  1024
#define DW_  300
#define H_   1024
#define BT_  (B_ * T_)   // 256

// ---------------- device scratch (no allocation allowed) ----------------
__device__ float g_a[BT_ * H_];        // fc_1 output [256,1024]
__device__ float g_w[C_ * H_];         // fc_2 output [527,1024]
__device__ float g_veff[H_];           // Wa @ W3 folded vector
__device__ float g_c0;                 // b3.Wa + ba
__device__ float g_score[BT_ * C_];    // [B*T, C]
__device__ float g_coef[BT_ * C_];     // softmax over T

__device__ __forceinline__ float tanh_fast(float x) {
    float y;
    asm("tanh.approx.f32 %0, %1;" : "=f"(y) : "f"(x));
    return y;
}

// ---------------- K1: veff + c0 prep ----------------
// blocks 0..15: veff chunk of 64 h each.  block 16: c0.
__global__ void prep_kernel(const float* __restrict__ W3, const float* __restrict__ Wa,
                            const float* __restrict__ b3, const float* __restrict__ ba) {
    __shared__ float sm[256];
    int tid = threadIdx.x;
    if (blockIdx.x < 16) {
        int hb = blockIdx.x * 64;
        int hl = tid & 63;
        int og = tid >> 6;             // 0..3
        float acc = 0.f;
        for (int o = og; o < H_; o += 4)
            acc += Wa[o] * W3[(size_t)o * H_ + hb + hl];
        sm[tid] = acc;
        __syncthreads();
        if (og == 0)
            g_veff[hb + hl] = sm[hl] + sm[64 + hl] + sm[128 + hl] + sm[192 + hl];
    } else {
        float acc = 0.f;
        for (int o = tid; o < H_; o += 256) acc += Wa[o] * b3[o];
        sm[tid] = acc;
        __syncthreads();
        for (int s = 128; s > 0; s >>= 1) {
            if (tid < s) sm[tid] += sm[tid + s];
            __syncthreads();
        }
        if (tid == 0) g_c0 = sm[0] + ba[0];
    }
}

// ---------------- K2/K3: C[M,N] = A[M,K] . B[N,K]^T ----------------
// tiles 32x64, Ktile 16, 128 threads, 4x4 microtile
__global__ void gemm_nt(const float* __restrict__ A, const float* __restrict__ B,
                        float* __restrict__ C, int M, int N, int K) {
    __shared__ float As[16][36];   // [k][m], pad to 36 (144B rows, 16B aligned)
    __shared__ float Bs[16][68];   // [k][n], pad to 68 (272B rows, 16B aligned)
    int tid = threadIdx.x;         // 128
    int tx = tid & 15;             // n quad 0..15
    int ty = tid >> 4;             // m quad 0..7
    int m0 = blockIdx.x * 32;
    int n0 = blockIdx.y * 64;
    float acc[4][4] = {};

    for (int k0 = 0; k0 < K; k0 += 16) {
        // A tile: 32x16, 4 per thread
        {
            int m  = tid >> 2;
            int kq = (tid & 3) * 4;
            int gm = m0 + m;
            bool mok = gm < M;
            const float* arow = A + (size_t)gm * K + k0 + kq;
#pragma unroll
            for (int i = 0; i < 4; i++) {
                int kk = k0 + kq + i;
                As[kq + i][m] = (mok && kk < K) ? arow[i] : 0.f;
            }
        }
        // B tile: 64x16, 8 per thread
        {
            int n  = tid >> 1;
            int kq = (tid & 1) * 8;
            int gn = n0 + n;
            bool nok = gn < N;
            const float* brow = B + (size_t)gn * K + k0 + kq;
#pragma unroll
            for (int i = 0; i < 8; i++) {
                int kk = k0 + kq + i;
                Bs[kq + i][n] = (nok && kk < K) ? brow[i] : 0.f;
            }
        }
        __syncthreads();
#pragma unroll
        for (int k = 0; k < 16; k++) {
            float4 a4 = *(const float4*)&As[k][ty * 4];
            float4 b4 = *(const float4*)&Bs[k][tx * 4];
            acc[0][0] += a4.x * b4.x; acc[0][1] += a4.x * b4.y; acc[0][2] += a4.x * b4.z; acc[0][3] += a4.x * b4.w;
            acc[1][0] += a4.y * b4.x; acc[1][1] += a4.y * b4.y; acc[1][2] += a4.y * b4.z; acc[1][3] += a4.y * b4.w;
            acc[2][0] += a4.z * b4.x; acc[2][1] += a4.z * b4.y; acc[2][2] += a4.z * b4.z; acc[2][3] += a4.z * b4.w;
            acc[3][0] += a4.w * b4.x; acc[3][1] += a4.w * b4.y; acc[3][2] += a4.w * b4.z; acc[3][3] += a4.w * b4.w;
        }
        __syncthreads();
    }
#pragma unroll
    for (int i = 0; i < 4; i++) {
        int gm = m0 + ty * 4 + i;
        if (gm >= M) continue;
#pragma unroll
        for (int j = 0; j < 4; j++) {
            int gn = n0 + tx * 4 + j;
            if (gn < N) C[(size_t)gm * N + gn] = acc[i][j];
        }
    }
}

// ---------------- K4: score[bt,c] = c0 + sum_h tanh(a[bt,h]*w[c,h])*veff[h] ----------------
// CTA: 8 bt-rows x 64 c.  256 threads: row = tid>>5 (bt), lane = tid&31 (c, c+32)
__global__ void score_kernel() {
    __shared__ float a_s[8][64];
    __shared__ float w_s[64][65];   // transposed [h][c], padded
    __shared__ float v_s[64];
    int tid  = threadIdx.x;
    int lane = tid & 31;
    int row  = tid >> 5;
    int bt0  = blockIdx.x * 8;
    int c0   = blockIdx.y * 64;
    float s0 = 0.f, s1 = 0.f;

    for (int h0 = 0; h0 < H_; h0 += 64) {
        // a tile: 8x64 = 512, 2 per thread
        {
            int i = tid;
            a_s[i >> 6][i & 63] = g_a[(bt0 + (i >> 6)) * H_ + h0 + (i & 63)];
            int i2 = tid + 256;
            a_s[i2 >> 6][i2 & 63] = g_a[(bt0 + (i2 >> 6)) * H_ + h0 + (i2 & 63)];
        }
        if (tid < 64) v_s[tid] = g_veff[h0 + tid];
        // w tile transposed: thread -> c = tid>>2 (0..63), q = tid&3 -> 16 h each
        {
            int c = tid >> 2, q = tid & 3;
            int cg = c0 + c;
            bool ok = cg < C_;
            const float* wrow = g_w + (size_t)cg * H_ + h0 + q * 16;
#pragma unroll
            for (int i = 0; i < 16; i++)
                w_s[q * 16 + i][c] = ok ? wrow[i] : 0.f;
        }
        __syncthreads();

        const float4* a4 = (const float4*)a_s[row];
        const float4* v4 = (const float4*)v_s;
#pragma unroll
        for (int hh = 0; hh < 16; hh++) {
            float4 av = a4[hh];
            float4 vv = v4[hh];
            int hb = hh * 4;
            float wa0 = w_s[hb + 0][lane];
            float wa1 = w_s[hb + 1][lane];
            float wa2 = w_s[hb + 2][lane];
            float wa3 = w_s[hb + 3][lane];
            float wb0 = w_s[hb + 0][lane + 32];
            float wb1 = w_s[hb + 1][lane + 32];
            float wb2 = w_s[hb + 2][lane + 32];
            float wb3 = w_s[hb + 3][lane + 32];
            s0 = fmaf(tanh_fast(av.x * wa0), vv.x, s0);
            s0 = fmaf(tanh_fast(av.y * wa1), vv.y, s0);
            s0 = fmaf(tanh_fast(av.z * wa2), vv.z, s0);
            s0 = fmaf(tanh_fast(av.w * wa3), vv.w, s0);
            s1 = fmaf(tanh_fast(av.x * wb0), vv.x, s1);
            s1 = fmaf(tanh_fast(av.y * wb1), vv.y, s1);
            s1 = fmaf(tanh_fast(av.z * wb2), vv.z, s1);
            s1 = fmaf(tanh_fast(av.w * wb3), vv.w, s1);
        }
        __syncthreads();
    }
    float c0v = g_c0;
    int ca = c0 + lane, cb = c0 + lane + 32;
    int base = (bt0 + row) * C_;
    if (ca < C_) g_score[base + ca] = s0 + c0v;
    if (cb < C_) g_score[base + cb] = s1 + c0v;
}

// ---------------- K5: softmax over T per (b,c) ----------------
__global__ void softmax_kernel() {
    int bc = blockIdx.x;           // b*C_ + c
    int b  = bc / C_;
    int c  = bc - b * C_;
    int t  = threadIdx.x;          // 128
    __shared__ float red[4], red2[4];

    float v = g_score[(b * T_ + t) * C_ + c];
    float m = v;
#pragma unroll
    for (int o = 16; o > 0; o >>= 1) m = fmaxf(m, __shfl_xor_sync(0xffffffffu, m, o));
    if ((t & 31) == 0) red[t >> 5] = m;
    __syncthreads();
    m = fmaxf(fmaxf(red[0], red[1]), fmaxf(red[2], red[3]));
    float e = __expf(v - m);
    float s = e;
#pragma unroll
    for (int o = 16; o > 0; o >>= 1) s += __shfl_xor_sync(0xffffffffu, s, o);
    if ((t & 31) == 0) red2[t >> 5] = s;
    __syncthreads();
    s = red2[0] + red2[1] + red2[2] + red2[3];
    g_coef[(b * T_ + t) * C_ + c] = e / s;
}

// ---------------- K6: out[b,c,d] = sum_t coef[b,t,c] * audio[b,t,d] ----------------
// per-b GEMM (TN form): tiles 32x64, K = T_ = 128
__global__ void pool_kernel(const float* __restrict__ audio, float* __restrict__ out) {
    __shared__ float As[16][36];   // [k][m] m over c
    __shared__ float Bs[16][68];   // [k][n] n over d
    int b   = blockIdx.z;
    const float* Acf = g_coef + (size_t)b * T_ * C_;
    const float* Bau = audio + (size_t)b * T_ * DA_;
    float* Cout = out + (size_t)b * C_ * DA_;
    int tid = threadIdx.x;         // 128
    int tx = tid & 15, ty = tid >> 4;
    int m0 = blockIdx.x * 32;
    int n0 = blockIdx.y * 64;
    float acc[4][4] = {};

    for (int k0 = 0; k0 < T_; k0 += 16) {
        // A: As[k][m] = coef[(k0+k)*C_ + m0+m], coalesced over m
        {
            int m = tid & 31;
            int kb = (tid >> 5) * 4;
            int gm = m0 + m;
            bool ok = gm < C_;
#pragma unroll
            for (int i = 0; i < 4; i++)
                As[kb + i][m] = ok ? Acf[(size_t)(k0 + kb + i) * C_ + gm] : 0.f;
        }
        // B: Bs[k][n] = audio[(k0+k)*DA_ + n0+n], coalesced over n
        {
            int n = tid & 63;
            int kb = (tid >> 6) * 8;
#pragma unroll
            for (int i = 0; i < 8; i++)
                Bs[kb + i][n] = Bau[(size_t)(k0 + kb + i) * DA_ + n0 + n];
        }
        __syncthreads();
#pragma unroll
        for (int k = 0; k < 16; k++) {
            float4 a4 = *(const float4*)&As[k][ty * 4];
            float4 b4 = *(const float4*)&Bs[k][tx * 4];
            acc[0][0] += a4.x * b4.x; acc[0][1] += a4.x * b4.y; acc[0][2] += a4.x * b4.z; acc[0][3] += a4.x * b4.w;
            acc[1][0] += a4.y * b4.x; acc[1][1] += a4.y * b4.y; acc[1][2] += a4.y * b4.z; acc[1][3] += a4.y * b4.w;
            acc[2][0] += a4.z * b4.x; acc[2][1] += a4.z * b4.y; acc[2][2] += a4.z * b4.z; acc[2][3] += a4.z * b4.w;
            acc[3][0] += a4.w * b4.x; acc[3][1] += a4.w * b4.y; acc[3][2] += a4.w * b4.z; acc[3][3] += a4.w * b4.w;
        }
        __syncthreads();
    }
#pragma unroll
    for (int i = 0; i < 4; i++) {
        int gm = m0 + ty * 4 + i;
        if (gm >= C_) continue;
#pragma unroll
        for (int j = 0; j < 4; j++) {
            int gn = n0 + tx * 4 + j;
            Cout[(size_t)gm * DA_ + gn] = acc[i][j];
        }
    }
}

// ---------------- launch ----------------
extern "C" void kernel_launch(void* const* d_in, const int* in_sizes, int n_in,
                              void* d_out, int out_size) {
    const float* audio = (const float*)d_in[0];   // [B,T,DA]
    const float* word  = (const float*)d_in[1];   // [C,DW]
    const float* W1    = (const float*)d_in[2];   // [H,DA]
    const float* W2    = (const float*)d_in[3];   // [H,DW]
    const float* W3    = (const float*)d_in[4];   // [H,H]
    const float* b3    = (const float*)d_in[5];   // [H]
    const float* Wa    = (const float*)d_in[6];   // [1,H]
    const float* ba    = (const float*)d_in[7];   // [1]
    float* out = (float*)d_out;                   // [B,C,DA]
    (void)in_sizes; (void)n_in; (void)out_size;

    void *pa = nullptr, *pw = nullptr;
    cudaGetSymbolAddress(&pa, g_a);
    cudaGetSymbolAddress(&pw, g_w);

    // K1: fold fc_3/fc_a into veff + c0
    prep_kernel<<<17, 256>>>(W3, Wa, b3, ba);
    // K2: a = audio @ W1^T   [256, 1024], K=1024
    gemm_nt<<<dim3(BT_ / 32, H_ / 64), 128>>>(audio, W1, (float*)pa, BT_, H_, DA_);
    // K3: w = word @ W2^T    [527, 1024], K=300
    gemm_nt<<<dim3((C_ + 31) / 32, H_ / 64), 128>>>(word, W2, (float*)pw, C_, H_, DW_);
    // K4: fused tanh-dot score
    score_kernel<<<dim3(BT_ / 8, (C_ + 63) / 64), 256>>>();
    // K5: softmax over T
    softmax_kernel<<<B_ * C_, T_>>>();
    // K6: softmax-weighted pooling
    pool_kernel<<<dim3((C_ + 31) / 32, DA_ / 64, B_), 128>>>(audio, out);
}

// round 2
// speedup vs baseline: 1.0941x; 1.0941x over previous
#include <cuda_runtime.h>
#include <cuda_bf16.h>

// Problem constants
#define B_   2
#define T_   128
#define C_   527
#define DA_  1024
#define DW_  300
#define H_   1024
#define BT_  (B_ * T_)   // 256

// ---------------- device scratch (no allocation allowed) ----------------
__device__ float g_a[BT_ * H_];        // fc_1 output [256,1024]
__device__ float g_w[C_ * H_];         // fc_2 output [527,1024]
__device__ float g_veff[H_];           // Wa @ W3 folded vector
__device__ float g_c0;                 // b3.Wa + ba
__device__ float g_score[BT_ * C_];    // [B*T, C]
__device__ float g_coef[BT_ * C_];     // softmax over T

__device__ __forceinline__ float tanh_fast(float x) {
    float y;
    asm("tanh.approx.f32 %0, %1;" : "=f"(y) : "f"(x));
    return y;
}

// ---------------- K1: veff + c0 prep ----------------
__global__ void prep_kernel(const float* __restrict__ W3, const float* __restrict__ Wa,
                            const float* __restrict__ b3, const float* __restrict__ ba) {
    __shared__ float sm[256];
    int tid = threadIdx.x;
    if (blockIdx.x < 16) {
        int hb = blockIdx.x * 64;
        int hl = tid & 63;
        int og = tid >> 6;             // 0..3
        float acc = 0.f;
        for (int o = og; o < H_; o += 4)
            acc += Wa[o] * W3[(size_t)o * H_ + hb + hl];
        sm[tid] = acc;
        __syncthreads();
        if (og == 0)
            g_veff[hb + hl] = sm[hl] + sm[64 + hl] + sm[128 + hl] + sm[192 + hl];
    } else {
        float acc = 0.f;
        for (int o = tid; o < H_; o += 256) acc += Wa[o] * b3[o];
        sm[tid] = acc;
        __syncthreads();
        for (int s = 128; s > 0; s >>= 1) {
            if (tid < s) sm[tid] += sm[tid + s];
            __syncthreads();
        }
        if (tid == 0) g_c0 = sm[0] + ba[0];
    }
}

// ---------------- K2/K3: C[M,N] = A[M,K] . B[N,K]^T ----------------
__global__ void gemm_nt(const float* __restrict__ A, const float* __restrict__ B,
                        float* __restrict__ C, int M, int N, int K) {
    __shared__ float As[16][36];
    __shared__ float Bs[16][68];
    int tid = threadIdx.x;         // 128
    int tx = tid & 15;
    int ty = tid >> 4;
    int m0 = blockIdx.x * 32;
    int n0 = blockIdx.y * 64;
    float acc[4][4] = {};

    for (int k0 = 0; k0 < K; k0 += 16) {
        {
            int m  = tid >> 2;
            int kq = (tid & 3) * 4;
            int gm = m0 + m;
            bool mok = gm < M;
            const float* arow = A + (size_t)gm * K + k0 + kq;
#pragma unroll
            for (int i = 0; i < 4; i++) {
                int kk = k0 + kq + i;
                As[kq + i][m] = (mok && kk < K) ? arow[i] : 0.f;
            }
        }
        {
            int n  = tid >> 1;
            int kq = (tid & 1) * 8;
            int gn = n0 + n;
            bool nok = gn < N;
            const float* brow = B + (size_t)gn * K + k0 + kq;
#pragma unroll
            for (int i = 0; i < 8; i++) {
                int kk = k0 + kq + i;
                Bs[kq + i][n] = (nok && kk < K) ? brow[i] : 0.f;
            }
        }
        __syncthreads();
#pragma unroll
        for (int k = 0; k < 16; k++) {
            float4 a4 = *(const float4*)&As[k][ty * 4];
            float4 b4 = *(const float4*)&Bs[k][tx * 4];
            acc[0][0] += a4.x * b4.x; acc[0][1] += a4.x * b4.y; acc[0][2] += a4.x * b4.z; acc[0][3] += a4.x * b4.w;
            acc[1][0] += a4.y * b4.x; acc[1][1] += a4.y * b4.y; acc[1][2] += a4.y * b4.z; acc[1][3] += a4.y * b4.w;
            acc[2][0] += a4.z * b4.x; acc[2][1] += a4.z * b4.y; acc[2][2] += a4.z * b4.z; acc[2][3] += a4.z * b4.w;
            acc[3][0] += a4.w * b4.x; acc[3][1] += a4.w * b4.y; acc[3][2] += a4.w * b4.z; acc[3][3] += a4.w * b4.w;
        }
        __syncthreads();
    }
#pragma unroll
    for (int i = 0; i < 4; i++) {
        int gm = m0 + ty * 4 + i;
        if (gm >= M) continue;
#pragma unroll
        for (int j = 0; j < 4; j++) {
            int gn = n0 + tx * 4 + j;
            if (gn < N) C[(size_t)gm * N + gn] = acc[i][j];
        }
    }
}

// ---------------- K4: score[bt,c] = c0 + sum_h tanh(a[bt,h]*w[c,h])*veff[h] ----------------
// CTA tile: 16 bt x 64 c, 256 threads. Thread: 2 bt (warp, warp+8) x 2 c (lane, lane+32).
// grid = (BT/16=16, ceil(C/64)=9) = 144 blocks -> ~1 CTA per SM, single balanced wave.
__global__ void score_kernel() {
    __shared__ float a_s[16][64];
    __shared__ float w_s[64][65];   // transposed [h][c], padded
    __shared__ float v_s[64];
    int tid  = threadIdx.x;
    int lane = tid & 31;
    int warp = tid >> 5;            // 0..7
    int bt0  = blockIdx.x * 16;
    int c0   = blockIdx.y * 64;
    float s00 = 0.f, s01 = 0.f, s10 = 0.f, s11 = 0.f;

    for (int h0 = 0; h0 < H_; h0 += 64) {
        // a tile: 16x64 floats = 256 float4, one per thread
        {
            int r = tid >> 4;              // 0..15
            int c4 = (tid & 15) * 4;       // 0..60
            *(float4*)&a_s[r][c4] = *(const float4*)&g_a[(size_t)(bt0 + r) * H_ + h0 + c4];
        }
        if (tid < 64) v_s[tid] = g_veff[h0 + tid];
        // w tile transposed: thread -> c = tid>>2 (0..63), q = tid&3 -> 16 h each
        {
            int c = tid >> 2, q = tid & 3;
            int cg = c0 + c;
            bool ok = cg < C_;
            const float* wrow = g_w + (size_t)cg * H_ + h0 + q * 16;
#pragma unroll
            for (int i = 0; i < 16; i++)
                w_s[q * 16 + i][c] = ok ? wrow[i] : 0.f;
        }
        __syncthreads();

        const float4* a4r0 = (const float4*)a_s[warp];       // bt row warp
        const float4* a4r1 = (const float4*)a_s[warp + 8];   // bt row warp+8
        const float4* v4   = (const float4*)v_s;
#pragma unroll
        for (int hh = 0; hh < 16; hh++) {
            float4 av0 = a4r0[hh];
            float4 av1 = a4r1[hh];
            float4 vv  = v4[hh];
            int hb = hh * 4;
            float wa0 = w_s[hb + 0][lane];
            float wa1 = w_s[hb + 1][lane];
            float wa2 = w_s[hb + 2][lane];
            float wa3 = w_s[hb + 3][lane];
            float wb0 = w_s[hb + 0][lane + 32];
            float wb1 = w_s[hb + 1][lane + 32];
            float wb2 = w_s[hb + 2][lane + 32];
            float wb3 = w_s[hb + 3][lane + 32];
            s00 = fmaf(tanh_fast(av0.x * wa0), vv.x, s00);
            s01 = fmaf(tanh_fast(av0.x * wb0), vv.x, s01);
            s10 = fmaf(tanh_fast(av1.x * wa0), vv.x, s10);
            s11 = fmaf(tanh_fast(av1.x * wb0), vv.x, s11);
            s00 = fmaf(tanh_fast(av0.y * wa1), vv.y, s00);
            s01 = fmaf(tanh_fast(av0.y * wb1), vv.y, s01);
            s10 = fmaf(tanh_fast(av1.y * wa1), vv.y, s10);
            s11 = fmaf(tanh_fast(av1.y * wb1), vv.y, s11);
            s00 = fmaf(tanh_fast(av0.z * wa2), vv.z, s00);
            s01 = fmaf(tanh_fast(av0.z * wb2), vv.z, s01);
            s10 = fmaf(tanh_fast(av1.z * wa2), vv.z, s10);
            s11 = fmaf(tanh_fast(av1.z * wb2), vv.z, s11);
            s00 = fmaf(tanh_fast(av0.w * wa3), vv.w, s00);
            s01 = fmaf(tanh_fast(av0.w * wb3), vv.w, s01);
            s10 = fmaf(tanh_fast(av1.w * wa3), vv.w, s10);
            s11 = fmaf(tanh_fast(av1.w * wb3), vv.w, s11);
        }
        __syncthreads();
    }
    float c0v = g_c0;
    int ca = c0 + lane, cb = c0 + lane + 32;
    int base0 = (bt0 + warp) * C_;
    int base1 = (bt0 + warp + 8) * C_;
    if (ca < C_) {
        g_score[base0 + ca] = s00 + c0v;
        g_score[base1 + ca] = s10 + c0v;
    }
    if (cb < C_) {
        g_score[base0 + cb] = s01 + c0v;
        g_score[base1 + cb] = s11 + c0v;
    }
}

// ---------------- K5: softmax over T per (b,c) ----------------
__global__ void softmax_kernel() {
    int bc = blockIdx.x;           // b*C_ + c
    int b  = bc / C_;
    int c  = bc - b * C_;
    int t  = threadIdx.x;          // 128
    __shared__ float red[4], red2[4];

    float v = g_score[(b * T_ + t) * C_ + c];
    float m = v;
#pragma unroll
    for (int o = 16; o > 0; o >>= 1) m = fmaxf(m, __shfl_xor_sync(0xffffffffu, m, o));
    if ((t & 31) == 0) red[t >> 5] = m;
    __syncthreads();
    m = fmaxf(fmaxf(red[0], red[1]), fmaxf(red[2], red[3]));
    float e = __expf(v - m);
    float s = e;
#pragma unroll
    for (int o = 16; o > 0; o >>= 1) s += __shfl_xor_sync(0xffffffffu, s, o);
    if ((t & 31) == 0) red2[t >> 5] = s;
    __syncthreads();
    s = red2[0] + red2[1] + red2[2] + red2[3];
    g_coef[(b * T_ + t) * C_ + c] = e / s;
}

// ---------------- K6: out[b,c,d] = sum_t coef[b,t,c] * audio[b,t,d] ----------------
__global__ void pool_kernel(const float* __restrict__ audio, float* __restrict__ out) {
    __shared__ float As[16][36];
    __shared__ float Bs[16][68];
    int b   = blockIdx.z;
    const float* Acf = g_coef + (size_t)b * T_ * C_;
    const float* Bau = audio + (size_t)b * T_ * DA_;
    float* Cout = out + (size_t)b * C_ * DA_;
    int tid = threadIdx.x;         // 128
    int tx = tid & 15, ty = tid >> 4;
    int m0 = blockIdx.x * 32;
    int n0 = blockIdx.y * 64;
    float acc[4][4] = {};

    for (int k0 = 0; k0 < T_; k0 += 16) {
        {
            int m = tid & 31;
            int kb = (tid >> 5) * 4;
            int gm = m0 + m;
            bool ok = gm < C_;
#pragma unroll
            for (int i = 0; i < 4; i++)
                As[kb + i][m] = ok ? Acf[(size_t)(k0 + kb + i) * C_ + gm] : 0.f;
        }
        {
            int n = tid & 63;
            int kb = (tid >> 6) * 8;
#pragma unroll
            for (int i = 0; i < 8; i++)
                Bs[kb + i][n] = Bau[(size_t)(k0 + kb + i) * DA_ + n0 + n];
        }
        __syncthreads();
#pragma unroll
        for (int k = 0; k < 16; k++) {
            float4 a4 = *(const float4*)&As[k][ty * 4];
            float4 b4 = *(const float4*)&Bs[k][tx * 4];
            acc[0][0] += a4.x * b4.x; acc[0][1] += a4.x * b4.y; acc[0][2] += a4.x * b4.z; acc[0][3] += a4.x * b4.w;
            acc[1][0] += a4.y * b4.x; acc[1][1] += a4.y * b4.y; acc[1][2] += a4.y * b4.z; acc[1][3] += a4.y * b4.w;
            acc[2][0] += a4.z * b4.x; acc[2][1] += a4.z * b4.y; acc[2][2] += a4.z * b4.z; acc[2][3] += a4.z * b4.w;
            acc[3][0] += a4.w * b4.x; acc[3][1] += a4.w * b4.y; acc[3][2] += a4.w * b4.z; acc[3][3] += a4.w * b4.w;
        }
        __syncthreads();
    }
#pragma unroll
    for (int i = 0; i < 4; i++) {
        int gm = m0 + ty * 4 + i;
        if (gm >= C_) continue;
#pragma unroll
        for (int j = 0; j < 4; j++) {
            int gn = n0 + tx * 4 + j;
            Cout[(size_t)gm * DA_ + gn] = acc[i][j];
        }
    }
}

// ---------------- launch ----------------
extern "C" void kernel_launch(void* const* d_in, const int* in_sizes, int n_in,
                              void* d_out, int out_size) {
    const float* audio = (const float*)d_in[0];   // [B,T,DA]
    const float* word  = (const float*)d_in[1];   // [C,DW]
    const float* W1    = (const float*)d_in[2];   // [H,DA]
    const float* W2    = (const float*)d_in[3];   // [H,DW]
    const float* W3    = (const float*)d_in[4];   // [H,H]
    const float* b3    = (const float*)d_in[5];   // [H]
    const float* Wa    = (const float*)d_in[6];   // [1,H]
    const float* ba    = (const float*)d_in[7];   // [1]
    float* out = (float*)d_out;                   // [B,C,DA]
    (void)in_sizes; (void)n_in; (void)out_size;

    void *pa = nullptr, *pw = nullptr;
    cudaGetSymbolAddress(&pa, g_a);
    cudaGetSymbolAddress(&pw, g_w);

    // K1: fold fc_3/fc_a into veff + c0
    prep_kernel<<<17, 256>>>(W3, Wa, b3, ba);
    // K2: a = audio @ W1^T   [256, 1024], K=1024
    gemm_nt<<<dim3(BT_ / 32, H_ / 64), 128>>>(audio, W1, (float*)pa, BT_, H_, DA_);
    // K3: w = word @ W2^T    [527, 1024], K=300
    gemm_nt<<<dim3((C_ + 31) / 32, H_ / 64), 128>>>(word, W2, (float*)pw, C_, H_, DW_);
    // K4: fused tanh-dot score (2bt x 2c register blocking)
    score_kernel<<<dim3(BT_ / 16, (C_ + 63) / 64), 256>>>();
    // K5: softmax over T
    softmax_kernel<<<B_ * C_, T_>>>();
    // K6: softmax-weighted pooling
    pool_kernel<<<dim3((C_ + 31) / 32, DA_ / 64, B_), 128>>>(audio, out);
}

// round 3
// speedup vs baseline: 1.2568x; 1.1486x over previous
#include <cuda_runtime.h>
#include <cuda_bf16.h>

// Problem constants
#define B_   2
#define T_   128
#define C_   527
#define DA_  1024
#define DW_  300
#define H_   1024
#define BT_  (B_ * T_)   // 256

// ---------------- device scratch ----------------
__device__ float g_a[BT_ * H_];          // fc_1 output [256,1024]
__device__ float g_w[C_ * H_];           // fc_2 output [527,1024]
__device__ float g_vpart[128 * H_];      // veff partials
__device__ float g_veff[H_];             // Wa @ W3 folded vector
__device__ float g_score0[BT_ * C_];     // partial score (h first half)
__device__ float g_score1[BT_ * C_];     // partial score (h second half)
__device__ float g_coef[BT_ * C_];       // softmax over T

__device__ __forceinline__ float tanh_fast(float x) {
    float y;
    asm("tanh.approx.f32 %0, %1;" : "=f"(y) : "f"(x));
    return y;
}

// ---------------- K1a: veff partials: block b handles o in [8b,8b+8) ----------------
__global__ void prep_part(const float* __restrict__ W3, const float* __restrict__ Wa) {
    __shared__ float wa8[8];
    int b = blockIdx.x, tid = threadIdx.x;
    if (tid < 8) wa8[tid] = Wa[b * 8 + tid];
    __syncthreads();
    for (int h = tid; h < H_; h += 256) {
        float acc = 0.f;
#pragma unroll
        for (int j = 0; j < 8; j++)
            acc += wa8[j] * W3[(size_t)(b * 8 + j) * H_ + h];
        g_vpart[b * H_ + h] = acc;
    }
}

// ---------------- K1b: reduce partials ----------------
__global__ void prep_reduce() {
    int h = blockIdx.x * 256 + threadIdx.x;
    float acc = 0.f;
#pragma unroll 8
    for (int p = 0; p < 128; p++) acc += g_vpart[p * H_ + h];
    g_veff[h] = acc;
}

// ---------------- K2/K3: C[M,N] = A[M,K] . B[N,K]^T, double-buffered ----------------
__global__ void gemm_nt(const float* __restrict__ A, const float* __restrict__ B,
                        float* __restrict__ C, int M, int N, int K) {
    __shared__ float As[16][36];
    __shared__ float Bs[16][68];
    int tid = threadIdx.x;         // 128
    int tx = tid & 15;
    int ty = tid >> 4;
    int m0 = blockIdx.x * 32;
    int n0 = blockIdx.y * 64;

    int am = tid >> 2, akq = (tid & 3) * 4;     // A: row am, k quad akq
    int bn = tid >> 1, bkq = (tid & 1) * 8;     // B: row bn, k oct bkq
    bool mok = (m0 + am) < M;
    bool nok = (n0 + bn) < N;
    const float* Abase = A + (size_t)(m0 + am) * K + akq;
    const float* Bbase = B + (size_t)(n0 + bn) * K + bkq;

    float ar[4], br[8];
    float acc[4][4] = {};

#pragma unroll
    for (int i = 0; i < 4; i++) ar[i] = (mok && akq + i < K) ? Abase[i] : 0.f;
#pragma unroll
    for (int i = 0; i < 8; i++) br[i] = (nok && bkq + i < K) ? Bbase[i] : 0.f;

    for (int k0 = 0; k0 < K; k0 += 16) {
#pragma unroll
        for (int i = 0; i < 4; i++) As[akq + i][am] = ar[i];
#pragma unroll
        for (int i = 0; i < 8; i++) Bs[bkq + i][bn] = br[i];
        __syncthreads();
        int kn = k0 + 16;
        if (kn < K) {
#pragma unroll
            for (int i = 0; i < 4; i++) ar[i] = (mok && kn + akq + i < K) ? Abase[kn + i] : 0.f;
#pragma unroll
            for (int i = 0; i < 8; i++) br[i] = (nok && kn + bkq + i < K) ? Bbase[kn + i] : 0.f;
        }
#pragma unroll
        for (int k = 0; k < 16; k++) {
            float4 a4 = *(const float4*)&As[k][ty * 4];
            float4 b4 = *(const float4*)&Bs[k][tx * 4];
            acc[0][0] += a4.x * b4.x; acc[0][1] += a4.x * b4.y; acc[0][2] += a4.x * b4.z; acc[0][3] += a4.x * b4.w;
            acc[1][0] += a4.y * b4.x; acc[1][1] += a4.y * b4.y; acc[1][2] += a4.y * b4.z; acc[1][3] += a4.y * b4.w;
            acc[2][0] += a4.z * b4.x; acc[2][1] += a4.z * b4.y; acc[2][2] += a4.z * b4.z; acc[2][3] += a4.z * b4.w;
            acc[3][0] += a4.w * b4.x; acc[3][1] += a4.w * b4.y; acc[3][2] += a4.w * b4.z; acc[3][3] += a4.w * b4.w;
        }
        __syncthreads();
    }
#pragma unroll
    for (int i = 0; i < 4; i++) {
        int gm = m0 + ty * 4 + i;
        if (gm >= M) continue;
#pragma unroll
        for (int j = 0; j < 4; j++) {
            int gn = n0 + tx * 4 + j;
            if (gn < N) C[(size_t)gm * N + gn] = acc[i][j];
        }
    }
}

// ---------------- K4: partial score over one H half ----------------
// CTA tile: 16 bt x 64 c, 256 threads, 2bt x 2c per thread. grid (16, 9, 2).
__global__ void __launch_bounds__(256, 2) score_kernel() {
    __shared__ float a_s[16][64];
    __shared__ float w_s[64][65];   // transposed [h][c], padded
    __shared__ float v_s[64];
    int tid  = threadIdx.x;
    int lane = tid & 31;
    int warp = tid >> 5;            // 0..7
    int bt0  = blockIdx.x * 16;
    int c0   = blockIdx.y * 64;
    int hb0  = blockIdx.z * (H_ / 2);
    float* out = blockIdx.z ? g_score1 : g_score0;
    float s00 = 0.f, s01 = 0.f, s10 = 0.f, s11 = 0.f;

    for (int h0 = hb0; h0 < hb0 + H_ / 2; h0 += 64) {
        {
            int r = tid >> 4;              // 0..15
            int c4 = (tid & 15) * 4;       // 0..60
            *(float4*)&a_s[r][c4] = *(const float4*)&g_a[(size_t)(bt0 + r) * H_ + h0 + c4];
        }
        if (tid < 64) v_s[tid] = g_veff[h0 + tid];
        {
            int c = tid >> 2, q = tid & 3;
            int cg = c0 + c;
            bool ok = cg < C_;
            const float* wrow = g_w + (size_t)cg * H_ + h0 + q * 16;
#pragma unroll
            for (int i = 0; i < 16; i++)
                w_s[q * 16 + i][c] = ok ? wrow[i] : 0.f;
        }
        __syncthreads();

        const float4* a4r0 = (const float4*)a_s[warp];
        const float4* a4r1 = (const float4*)a_s[warp + 8];
        const float4* v4   = (const float4*)v_s;
#pragma unroll
        for (int hh = 0; hh < 16; hh++) {
            float4 av0 = a4r0[hh];
            float4 av1 = a4r1[hh];
            float4 vv  = v4[hh];
            int hb = hh * 4;
            float wa0 = w_s[hb + 0][lane];
            float wa1 = w_s[hb + 1][lane];
            float wa2 = w_s[hb + 2][lane];
            float wa3 = w_s[hb + 3][lane];
            float wb0 = w_s[hb + 0][lane + 32];
            float wb1 = w_s[hb + 1][lane + 32];
            float wb2 = w_s[hb + 2][lane + 32];
            float wb3 = w_s[hb + 3][lane + 32];
            s00 = fmaf(tanh_fast(av0.x * wa0), vv.x, s00);
            s01 = fmaf(tanh_fast(av0.x * wb0), vv.x, s01);
            s10 = fmaf(tanh_fast(av1.x * wa0), vv.x, s10);
            s11 = fmaf(tanh_fast(av1.x * wb0), vv.x, s11);
            s00 = fmaf(tanh_fast(av0.y * wa1), vv.y, s00);
            s01 = fmaf(tanh_fast(av0.y * wb1), vv.y, s01);
            s10 = fmaf(tanh_fast(av1.y * wa1), vv.y, s10);
            s11 = fmaf(tanh_fast(av1.y * wb1), vv.y, s11);
            s00 = fmaf(tanh_fast(av0.z * wa2), vv.z, s00);
            s01 = fmaf(tanh_fast(av0.z * wb2), vv.z, s01);
            s10 = fmaf(tanh_fast(av1.z * wa2), vv.z, s10);
            s11 = fmaf(tanh_fast(av1.z * wb2), vv.z, s11);
            s00 = fmaf(tanh_fast(av0.w * wa3), vv.w, s00);
            s01 = fmaf(tanh_fast(av0.w * wb3), vv.w, s01);
            s10 = fmaf(tanh_fast(av1.w * wa3), vv.w, s10);
            s11 = fmaf(tanh_fast(av1.w * wb3), vv.w, s11);
        }
        __syncthreads();
    }
    int ca = c0 + lane, cb = c0 + lane + 32;
    int base0 = (bt0 + warp) * C_;
    int base1 = (bt0 + warp + 8) * C_;
    if (ca < C_) {
        out[base0 + ca] = s00;
        out[base1 + ca] = s10;
    }
    if (cb < C_) {
        out[base0 + cb] = s01;
        out[base1 + cb] = s11;
    }
}

// ---------------- K5: softmax over T per (b,c), merging the two partials ----------------
__global__ void softmax_kernel() {
    int bc = blockIdx.x;           // b*C_ + c
    int b  = bc / C_;
    int c  = bc - b * C_;
    int t  = threadIdx.x;          // 128
    __shared__ float red[4], red2[4];

    int idx = (b * T_ + t) * C_ + c;
    float v = g_score0[idx] + g_score1[idx];
    float m = v;
#pragma unroll
    for (int o = 16; o > 0; o >>= 1) m = fmaxf(m, __shfl_xor_sync(0xffffffffu, m, o));
    if ((t & 31) == 0) red[t >> 5] = m;
    __syncthreads();
    m = fmaxf(fmaxf(red[0], red[1]), fmaxf(red[2], red[3]));
    float e = __expf(v - m);
    float s = e;
#pragma unroll
    for (int o = 16; o > 0; o >>= 1) s += __shfl_xor_sync(0xffffffffu, s, o);
    if ((t & 31) == 0) red2[t >> 5] = s;
    __syncthreads();
    s = red2[0] + red2[1] + red2[2] + red2[3];
    g_coef[idx] = e / s;
}

// ---------------- K6: out[b,c,d] = sum_t coef[b,t,c] * audio[b,t,d], double-buffered ----------------
__global__ void pool_kernel(const float* __restrict__ audio, float* __restrict__ out) {
    __shared__ float As[16][36];
    __shared__ float Bs[16][68];
    int b   = blockIdx.z;
    const float* Acf = g_coef + (size_t)b * T_ * C_;
    const float* Bau = audio + (size_t)b * T_ * DA_;
    float* Cout = out + (size_t)b * C_ * DA_;
    int tid = threadIdx.x;         // 128
    int tx = tid & 15, ty = tid >> 4;
    int m0 = blockIdx.x * 32;
    int n0 = blockIdx.y * 64;

    int am = tid & 31, akb = (tid >> 5) * 4;    // A: col m=am, k rows akb..akb+3
    int bnn = tid & 63, bkb = (tid >> 6) * 8;   // B: col n=bnn, k rows bkb..bkb+7
    bool mok = (m0 + am) < C_;
    float ar[4], br[8];
    float acc[4][4] = {};

#pragma unroll
    for (int i = 0; i < 4; i++)
        ar[i] = mok ? Acf[(size_t)(akb + i) * C_ + m0 + am] : 0.f;
#pragma unroll
    for (int i = 0; i < 8; i++)
        br[i] = Bau[(size_t)(bkb + i) * DA_ + n0 + bnn];

    for (int k0 = 0; k0 < T_; k0 += 16) {
#pragma unroll
        for (int i = 0; i < 4; i++) As[akb + i][am] = ar[i];
#pragma unroll
        for (int i = 0; i < 8; i++) Bs[bkb + i][bnn] = br[i];
        __syncthreads();
        int kn = k0 + 16;
        if (kn < T_) {
#pragma unroll
            for (int i = 0; i < 4; i++)
                ar[i] = mok ? Acf[(size_t)(kn + akb + i) * C_ + m0 + am] : 0.f;
#pragma unroll
            for (int i = 0; i < 8; i++)
                br[i] = Bau[(size_t)(kn + bkb + i) * DA_ + n0 + bnn];
        }
#pragma unroll
        for (int k = 0; k < 16; k++) {
            float4 a4 = *(const float4*)&As[k][ty * 4];
            float4 b4 = *(const float4*)&Bs[k][tx * 4];
            acc[0][0] += a4.x * b4.x; acc[0][1] += a4.x * b4.y; acc[0][2] += a4.x * b4.z; acc[0][3] += a4.x * b4.w;
            acc[1][0] += a4.y * b4.x; acc[1][1] += a4.y * b4.y; acc[1][2] += a4.y * b4.z; acc[1][3] += a4.y * b4.w;
            acc[2][0] += a4.z * b4.x; acc[2][1] += a4.z * b4.y; acc[2][2] += a4.z * b4.z; acc[2][3] += a4.z * b4.w;
            acc[3][0] += a4.w * b4.x; acc[3][1] += a4.w * b4.y; acc[3][2] += a4.w * b4.z; acc[3][3] += a4.w * b4.w;
        }
        __syncthreads();
    }
#pragma unroll
    for (int i = 0; i < 4; i++) {
        int gm = m0 + ty * 4 + i;
        if (gm >= C_) continue;
#pragma unroll
        for (int j = 0; j < 4; j++) {
            int gn = n0 + tx * 4 + j;
            Cout[(size_t)gm * DA_ + gn] = acc[i][j];
        }
    }
}

// ---------------- launch ----------------
extern "C" void kernel_launch(void* const* d_in, const int* in_sizes, int n_in,
                              void* d_out, int out_size) {
    const float* audio = (const float*)d_in[0];   // [B,T,DA]
    const float* word  = (const float*)d_in[1];   // [C,DW]
    const float* W1    = (const float*)d_in[2];   // [H,DA]
    const float* W2    = (const float*)d_in[3];   // [H,DW]
    const float* W3    = (const float*)d_in[4];   // [H,H]
    const float* Wa    = (const float*)d_in[6];   // [1,H]
    float* out = (float*)d_out;                   // [B,C,DA]
    (void)in_sizes; (void)n_in; (void)out_size;

    void *pa = nullptr, *pw = nullptr;
    cudaGetSymbolAddress(&pa, g_a);
    cudaGetSymbolAddress(&pw, g_w);

    // K1: veff = Wa @ W3 (two-stage, deterministic)
    prep_part<<<128, 256>>>(W3, Wa);
    prep_reduce<<<H_ / 256, 256>>>();
    // K2: a = audio @ W1^T   [256, 1024], K=1024
    gemm_nt<<<dim3(BT_ / 32, H_ / 64), 128>>>(audio, W1, (float*)pa, BT_, H_, DA_);
    // K3: w = word @ W2^T    [527, 1024], K=300
    gemm_nt<<<dim3((C_ + 31) / 32, H_ / 64), 128>>>(word, W2, (float*)pw, C_, H_, DW_);
    // K4: fused tanh-dot score, split over H halves
    score_kernel<<<dim3(BT_ / 16, (C_ + 63) / 64, 2), 256>>>();
    // K5: softmax over T (merges partials; constant bias cancels)
    softmax_kernel<<<B_ * C_, T_>>>();
    // K6: softmax-weighted pooling
    pool_kernel<<<dim3((C_ + 31) / 32, DA_ / 64, B_), 128>>>(audio, out);
}

// round 4
// speedup vs baseline: 1.3478x; 1.0725x over previous
#include <cuda_runtime.h>
#include <cuda_bf16.h>

// Problem constants
#define B_   2
#define T_   128
#define C_   527
#define DA_  1024
#define DW_  300
#define H_   1024
#define BT_  (B_ * T_)   // 256

typedef unsigned long long u64;

// ---------------- device scratch ----------------
__device__ float g_a[BT_ * H_];          // fc_1 output [256,1024]
__device__ float g_apart[2 * BT_ * H_];  // split-K partials for fc_1
__device__ float g_w[C_ * H_];           // fc_2 output [527,1024]
__device__ float g_vpart[128 * H_];      // veff partials
__device__ float g_veff[H_];             // Wa @ W3 folded vector
__device__ float g_score0[BT_ * C_];     // partial score (h first half)
__device__ float g_score1[BT_ * C_];     // partial score (h second half)
__device__ float g_coef[BT_ * C_];       // softmax over T

__device__ __forceinline__ float tanh_fast(float x) {
    float y;
    asm("tanh.approx.f32 %0, %1;" : "=f"(y) : "f"(x));
    return y;
}

__device__ __forceinline__ void fma2(u64& d, u64 a, u64 b) {
    asm("fma.rn.f32x2 %0, %1, %2, %0;" : "+l"(d) : "l"(a), "l"(b));
}
__device__ __forceinline__ float unpk_sum(u64 v) {
    float lo, hi;
    asm("mov.b64 {%0,%1}, %2;" : "=f"(lo), "=f"(hi) : "l"(v));
    return lo + hi;
}

// ---------------- K1a: veff partials: block b handles o in [8b,8b+8) ----------------
__global__ void prep_part(const float* __restrict__ W3, const float* __restrict__ Wa) {
    __shared__ float wa8[8];
    int b = blockIdx.x, tid = threadIdx.x;
    if (tid < 8) wa8[tid] = Wa[b * 8 + tid];
    __syncthreads();
    for (int h = tid; h < H_; h += 256) {
        float acc = 0.f;
#pragma unroll
        for (int j = 0; j < 8; j++)
            acc += wa8[j] * W3[(size_t)(b * 8 + j) * H_ + h];
        g_vpart[b * H_ + h] = acc;
    }
}

// ---------------- K1b: reduce partials ----------------
__global__ void prep_reduce() {
    int h = blockIdx.x * 256 + threadIdx.x;
    float acc = 0.f;
#pragma unroll 8
    for (int p = 0; p < 128; p++) acc += g_vpart[p * H_ + h];
    g_veff[h] = acc;
}

// ---------------- GEMM v2: C[M,N] = A[M,K] . B[N,K]^T ----------------
// 64x64 tile, 128 threads, 8m x 4n microtile, f32x2 k-paired accumulation.
// blockIdx.z = split-K chunk (chunk size Kc); output offset z*M*N.
__global__ void __launch_bounds__(128) gemm_nt2(const float* __restrict__ A,
                                                const float* __restrict__ B,
                                                float* __restrict__ C,
                                                int M, int N, int K, int Kc) {
    __shared__ float As2[8 * 128];   // [k2][m][2]
    __shared__ float Bs2[8 * 128];   // [k2][n][2]
    int tid = threadIdx.x;
    int m0 = blockIdx.x * 64;
    int n0 = blockIdx.y * 64;
    int k0g = blockIdx.z * Kc;
    int Kend = min(k0g + Kc, K);
    float* Cout = C + (size_t)blockIdx.z * M * N;

    int lr = tid >> 1;             // 0..63 tile row
    int lk = (tid & 1) * 8;        // k offset 0/8
    int k2b = lk >> 1;             // 0 or 4
    int gmA = min(m0 + lr, M - 1);
    const float* Ap = A + (size_t)gmA * K + lk;
    const float* Bp = B + (size_t)(n0 + lr) * K + lk;

    int tx = tid & 15;             // n = n0 + tx*4
    int ty = tid >> 4;             // m = m0 + ty*8

    u64 acc[8][4];
#pragma unroll
    for (int i = 0; i < 8; i++)
#pragma unroll
        for (int j = 0; j < 4; j++) acc[i][j] = 0ull;

    float4 a0, a1, b0, b1;
    // initial load (tile k0g)
    {
        int kk = k0g;
        if (kk + 16 <= Kend) {
            a0 = *(const float4*)(Ap + kk); a1 = *(const float4*)(Ap + kk + 4);
            b0 = *(const float4*)(Bp + kk); b1 = *(const float4*)(Bp + kk + 4);
        } else {
            float t[8];
#pragma unroll
            for (int i = 0; i < 8; i++) t[i] = (kk + lk + i < Kend) ? Ap[kk + i] : 0.f;
            a0 = make_float4(t[0], t[1], t[2], t[3]); a1 = make_float4(t[4], t[5], t[6], t[7]);
#pragma unroll
            for (int i = 0; i < 8; i++) t[i] = (kk + lk + i < Kend) ? Bp[kk + i] : 0.f;
            b0 = make_float4(t[0], t[1], t[2], t[3]); b1 = make_float4(t[4], t[5], t[6], t[7]);
        }
    }

    for (int k0 = k0g; k0 < Kend; k0 += 16) {
        // store current tile into smem (k-pair interleaved)
        *(float2*)&As2[(k2b + 0) * 128 + lr * 2] = make_float2(a0.x, a0.y);
        *(float2*)&As2[(k2b + 1) * 128 + lr * 2] = make_float2(a0.z, a0.w);
        *(float2*)&As2[(k2b + 2) * 128 + lr * 2] = make_float2(a1.x, a1.y);
        *(float2*)&As2[(k2b + 3) * 128 + lr * 2] = make_float2(a1.z, a1.w);
        *(float2*)&Bs2[(k2b + 0) * 128 + lr * 2] = make_float2(b0.x, b0.y);
        *(float2*)&Bs2[(k2b + 1) * 128 + lr * 2] = make_float2(b0.z, b0.w);
        *(float2*)&Bs2[(k2b + 2) * 128 + lr * 2] = make_float2(b1.x, b1.y);
        *(float2*)&Bs2[(k2b + 3) * 128 + lr * 2] = make_float2(b1.z, b1.w);
        __syncthreads();

        // prefetch next tile into registers
        float4 na0, na1, nb0, nb1;
        int kn = k0 + 16;
        bool more = kn < Kend;
        if (more) {
            if (kn + 16 <= Kend) {
                na0 = *(const float4*)(Ap + kn); na1 = *(const float4*)(Ap + kn + 4);
                nb0 = *(const float4*)(Bp + kn); nb1 = *(const float4*)(Bp + kn + 4);
            } else {
                float t[8];
#pragma unroll
                for (int i = 0; i < 8; i++) t[i] = (kn + lk + i < Kend) ? Ap[kn + i] : 0.f;
                na0 = make_float4(t[0], t[1], t[2], t[3]); na1 = make_float4(t[4], t[5], t[6], t[7]);
#pragma unroll
                for (int i = 0; i < 8; i++) t[i] = (kn + lk + i < Kend) ? Bp[kn + i] : 0.f;
                nb0 = make_float4(t[0], t[1], t[2], t[3]); nb1 = make_float4(t[4], t[5], t[6], t[7]);
            }
        }

#pragma unroll
        for (int k2 = 0; k2 < 8; k2++) {
            ulonglong2 A01 = *(const ulonglong2*)&As2[k2 * 128 + ty * 16];
            ulonglong2 A23 = *(const ulonglong2*)&As2[k2 * 128 + ty * 16 + 4];
            ulonglong2 A45 = *(const ulonglong2*)&As2[k2 * 128 + ty * 16 + 8];
            ulonglong2 A67 = *(const ulonglong2*)&As2[k2 * 128 + ty * 16 + 12];
            ulonglong2 B01 = *(const ulonglong2*)&Bs2[k2 * 128 + tx * 8];
            ulonglong2 B23 = *(const ulonglong2*)&Bs2[k2 * 128 + tx * 8 + 4];
            u64 am[8] = {A01.x, A01.y, A23.x, A23.y, A45.x, A45.y, A67.x, A67.y};
            u64 bn[4] = {B01.x, B01.y, B23.x, B23.y};
#pragma unroll
            for (int i = 0; i < 8; i++) {
                fma2(acc[i][0], am[i], bn[0]);
                fma2(acc[i][1], am[i], bn[1]);
                fma2(acc[i][2], am[i], bn[2]);
                fma2(acc[i][3], am[i], bn[3]);
            }
        }
        __syncthreads();
        if (more) { a0 = na0; a1 = na1; b0 = nb0; b1 = nb1; }
    }

#pragma unroll
    for (int i = 0; i < 8; i++) {
        int gm = m0 + ty * 8 + i;
        if (gm >= M) continue;
        float4 o;
        o.x = unpk_sum(acc[i][0]);
        o.y = unpk_sum(acc[i][1]);
        o.z = unpk_sum(acc[i][2]);
        o.w = unpk_sum(acc[i][3]);
        *(float4*)&Cout[(size_t)gm * N + n0 + tx * 4] = o;
    }
}

// ---------------- reduce the 2 split-K partials of fc_1 ----------------
__global__ void reduce2_kernel() {
    int i = (blockIdx.x * 256 + threadIdx.x) * 4;
    float4 x = *(float4*)&g_apart[i];
    float4 y = *(float4*)&g_apart[BT_ * H_ + i];
    x.x += y.x; x.y += y.y; x.z += y.z; x.w += y.w;
    *(float4*)&g_a[i] = x;
}

// ---------------- K4: partial score over one H half ----------------
// CTA tile: 16 bt x 64 c, 256 threads, 2bt x 2c per thread. grid (16, 9, 2).
__global__ void __launch_bounds__(256, 2) score_kernel() {
    __shared__ float a_s[16][64];
    __shared__ float w_s[64][65];   // transposed [h][c], padded
    __shared__ float v_s[64];
    int tid  = threadIdx.x;
    int lane = tid & 31;
    int warp = tid >> 5;            // 0..7
    int bt0  = blockIdx.x * 16;
    int c0   = blockIdx.y * 64;
    int hb0  = blockIdx.z * (H_ / 2);
    float* out = blockIdx.z ? g_score1 : g_score0;
    float s00 = 0.f, s01 = 0.f, s10 = 0.f, s11 = 0.f;

    for (int h0 = hb0; h0 < hb0 + H_ / 2; h0 += 64) {
        {
            int r = tid >> 4;              // 0..15
            int c4 = (tid & 15) * 4;       // 0..60
            *(float4*)&a_s[r][c4] = *(const float4*)&g_a[(size_t)(bt0 + r) * H_ + h0 + c4];
        }
        if (tid < 64) v_s[tid] = g_veff[h0 + tid];
        {
            int c = tid >> 2, q = tid & 3;
            int cg = c0 + c;
            bool ok = cg < C_;
            const float* wrow = g_w + (size_t)cg * H_ + h0 + q * 16;
#pragma unroll
            for (int i = 0; i < 16; i++)
                w_s[q * 16 + i][c] = ok ? wrow[i] : 0.f;
        }
        __syncthreads();

        const float4* a4r0 = (const float4*)a_s[warp];
        const float4* a4r1 = (const float4*)a_s[warp + 8];
        const float4* v4   = (const float4*)v_s;
#pragma unroll
        for (int hh = 0; hh < 16; hh++) {
            float4 av0 = a4r0[hh];
            float4 av1 = a4r1[hh];
            float4 vv  = v4[hh];
            int hb = hh * 4;
            float wa0 = w_s[hb + 0][lane];
            float wa1 = w_s[hb + 1][lane];
            float wa2 = w_s[hb + 2][lane];
            float wa3 = w_s[hb + 3][lane];
            float wb0 = w_s[hb + 0][lane + 32];
            float wb1 = w_s[hb + 1][lane + 32];
            float wb2 = w_s[hb + 2][lane + 32];
            float wb3 = w_s[hb + 3][lane + 32];
            s00 = fmaf(tanh_fast(av0.x * wa0), vv.x, s00);
            s01 = fmaf(tanh_fast(av0.x * wb0), vv.x, s01);
            s10 = fmaf(tanh_fast(av1.x * wa0), vv.x, s10);
            s11 = fmaf(tanh_fast(av1.x * wb0), vv.x, s11);
            s00 = fmaf(tanh_fast(av0.y * wa1), vv.y, s00);
            s01 = fmaf(tanh_fast(av0.y * wb1), vv.y, s01);
            s10 = fmaf(tanh_fast(av1.y * wa1), vv.y, s10);
            s11 = fmaf(tanh_fast(av1.y * wb1), vv.y, s11);
            s00 = fmaf(tanh_fast(av0.z * wa2), vv.z, s00);
            s01 = fmaf(tanh_fast(av0.z * wb2), vv.z, s01);
            s10 = fmaf(tanh_fast(av1.z * wa2), vv.z, s10);
            s11 = fmaf(tanh_fast(av1.z * wb2), vv.z, s11);
            s00 = fmaf(tanh_fast(av0.w * wa3), vv.w, s00);
            s01 = fmaf(tanh_fast(av0.w * wb3), vv.w, s01);
            s10 = fmaf(tanh_fast(av1.w * wa3), vv.w, s10);
            s11 = fmaf(tanh_fast(av1.w * wb3), vv.w, s11);
        }
        __syncthreads();
    }
    int ca = c0 + lane, cb = c0 + lane + 32;
    int base0 = (bt0 + warp) * C_;
    int base1 = (bt0 + warp + 8) * C_;
    if (ca < C_) {
        out[base0 + ca] = s00;
        out[base1 + ca] = s10;
    }
    if (cb < C_) {
        out[base0 + cb] = s01;
        out[base1 + cb] = s11;
    }
}

// ---------------- K5: softmax over T per (b,c), merging the two partials ----------------
__global__ void softmax_kernel() {
    int bc = blockIdx.x;           // b*C_ + c
    int b  = bc / C_;
    int c  = bc - b * C_;
    int t  = threadIdx.x;          // 128
    __shared__ float red[4], red2[4];

    int idx = (b * T_ + t) * C_ + c;
    float v = g_score0[idx] + g_score1[idx];
    float m = v;
#pragma unroll
    for (int o = 16; o > 0; o >>= 1) m = fmaxf(m, __shfl_xor_sync(0xffffffffu, m, o));
    if ((t & 31) == 0) red[t >> 5] = m;
    __syncthreads();
    m = fmaxf(fmaxf(red[0], red[1]), fmaxf(red[2], red[3]));
    float e = __expf(v - m);
    float s = e;
#pragma unroll
    for (int o = 16; o > 0; o >>= 1) s += __shfl_xor_sync(0xffffffffu, s, o);
    if ((t & 31) == 0) red2[t >> 5] = s;
    __syncthreads();
    s = red2[0] + red2[1] + red2[2] + red2[3];
    g_coef[idx] = e / s;
}

// ---------------- K6 v2: out[b,c,d] = sum_t coef[b,t,c] * audio[b,t,d] ----------------
// TN form: both operands K-major. 64x64 tile, 128 threads, 8x4 micro, f32x2.
__global__ void __launch_bounds__(128) pool2(const float* __restrict__ audio,
                                             float* __restrict__ out) {
    __shared__ float As2[8 * 128];   // [k2][c][2]
    __shared__ float Bs2[8 * 128];   // [k2][d][2]
    int b = blockIdx.z;
    const float* coefb = g_coef + (size_t)b * T_ * C_;
    const float* audb  = audio + (size_t)b * T_ * DA_;
    float* Cout = out + (size_t)b * C_ * DA_;
    int tid = threadIdx.x;
    int m0 = blockIdx.x * 64;
    int n0 = blockIdx.y * 64;

    int lm  = tid & 63;            // tile col (m for A, n for B)
    int lkg = tid >> 6;            // 0/1 -> k2 group of 4
    int gm  = min(m0 + lm, C_ - 1);

    int tx = tid & 15, ty = tid >> 4;

    u64 acc[8][4];
#pragma unroll
    for (int i = 0; i < 8; i++)
#pragma unroll
        for (int j = 0; j < 4; j++) acc[i][j] = 0ull;

    float2 pa[4], pb[4];
#pragma unroll
    for (int i = 0; i < 4; i++) {
        int ke = lkg * 8 + 2 * i;
        pa[i] = make_float2(coefb[(size_t)ke * C_ + gm], coefb[(size_t)(ke + 1) * C_ + gm]);
        pb[i] = make_float2(audb[(size_t)ke * DA_ + n0 + lm], audb[(size_t)(ke + 1) * DA_ + n0 + lm]);
    }

    for (int k0 = 0; k0 < T_; k0 += 16) {
#pragma unroll
        for (int i = 0; i < 4; i++) {
            *(float2*)&As2[(lkg * 4 + i) * 128 + lm * 2] = pa[i];
            *(float2*)&Bs2[(lkg * 4 + i) * 128 + lm * 2] = pb[i];
        }
        __syncthreads();
        int kn = k0 + 16;
        if (kn < T_) {
#pragma unroll
            for (int i = 0; i < 4; i++) {
                int ke = kn + lkg * 8 + 2 * i;
                pa[i] = make_float2(coefb[(size_t)ke * C_ + gm], coefb[(size_t)(ke + 1) * C_ + gm]);
                pb[i] = make_float2(audb[(size_t)ke * DA_ + n0 + lm], audb[(size_t)(ke + 1) * DA_ + n0 + lm]);
            }
        }
#pragma unroll
        for (int k2 = 0; k2 < 8; k2++) {
            ulonglong2 A01 = *(const ulonglong2*)&As2[k2 * 128 + ty * 16];
            ulonglong2 A23 = *(const ulonglong2*)&As2[k2 * 128 + ty * 16 + 4];
            ulonglong2 A45 = *(const ulonglong2*)&As2[k2 * 128 + ty * 16 + 8];
            ulonglong2 A67 = *(const ulonglong2*)&As2[k2 * 128 + ty * 16 + 12];
            ulonglong2 B01 = *(const ulonglong2*)&Bs2[k2 * 128 + tx * 8];
            ulonglong2 B23 = *(const ulonglong2*)&Bs2[k2 * 128 + tx * 8 + 4];
            u64 am[8] = {A01.x, A01.y, A23.x, A23.y, A45.x, A45.y, A67.x, A67.y};
            u64 bn[4] = {B01.x, B01.y, B23.x, B23.y};
#pragma unroll
            for (int i = 0; i < 8; i++) {
                fma2(acc[i][0], am[i], bn[0]);
                fma2(acc[i][1], am[i], bn[1]);
                fma2(acc[i][2], am[i], bn[2]);
                fma2(acc[i][3], am[i], bn[3]);
            }
        }
        __syncthreads();
    }

#pragma unroll
    for (int i = 0; i < 8; i++) {
        int gm2 = m0 + ty * 8 + i;
        if (gm2 >= C_) continue;
        float4 o;
        o.x = unpk_sum(acc[i][0]);
        o.y = unpk_sum(acc[i][1]);
        o.z = unpk_sum(acc[i][2]);
        o.w = unpk_sum(acc[i][3]);
        *(float4*)&Cout[(size_t)gm2 * DA_ + n0 + tx * 4] = o;
    }
}

// ---------------- launch ----------------
extern "C" void kernel_launch(void* const* d_in, const int* in_sizes, int n_in,
                              void* d_out, int out_size) {
    const float* audio = (const float*)d_in[0];   // [B,T,DA]
    const float* word  = (const float*)d_in[1];   // [C,DW]
    const float* W1    = (const float*)d_in[2];   // [H,DA]
    const float* W2    = (const float*)d_in[3];   // [H,DW]
    const float* W3    = (const float*)d_in[4];   // [H,H]
    const float* Wa    = (const float*)d_in[6];   // [1,H]
    float* out = (float*)d_out;                   // [B,C,DA]
    (void)in_sizes; (void)n_in; (void)out_size;

    void *papart = nullptr, *pw = nullptr;
    cudaGetSymbolAddress(&papart, g_apart);
    cudaGetSymbolAddress(&pw, g_w);

    // K1: veff = Wa @ W3 (two-stage, deterministic)
    prep_part<<<128, 256>>>(W3, Wa);
    prep_reduce<<<H_ / 256, 256>>>();
    // K2: a = audio @ W1^T [256,1024], K=1024, split-K 2 + reduce
    gemm_nt2<<<dim3(BT_ / 64, H_ / 64, 2), 128>>>(audio, W1, (float*)papart, BT_, H_, DA_, DA_ / 2);
    reduce2_kernel<<<BT_ * H_ / 1024, 256>>>();
    // K3: w = word @ W2^T [527,1024], K=300
    gemm_nt2<<<dim3((C_ + 63) / 64, H_ / 64, 1), 128>>>(word, W2, (float*)pw, C_, H_, DW_, DW_);
    // K4: fused tanh-dot score, split over H halves
    score_kernel<<<dim3(BT_ / 16, (C_ + 63) / 64, 2), 256>>>();
    // K5: softmax over T (merges partials; constant bias cancels)
    softmax_kernel<<<B_ * C_, T_>>>();
    // K6: softmax-weighted pooling (f32x2 TN GEMM)
    pool2<<<dim3((C_ + 63) / 64, DA_ / 64, B_), 128>>>(audio, out);
}

// round 5
// speedup vs baseline: 1.4996x; 1.1126x over previous
#include <cuda_runtime.h>
#include <cuda_bf16.h>

// Problem constants
#define B_   2
#define T_   128
#define C_   527
#define DA_  1024
#define DW_  300
#define H_   1024
#define BT_  (B_ * T_)   // 256

typedef unsigned long long u64;

// ---------------- device scratch ----------------
__device__ float g_apart[2 * BT_ * H_];  // split-K partials for fc_1
__device__ float g_w[C_ * H_];           // fc_2 output [527,1024]
__device__ float g_veff[H_];             // Wa @ W3 folded vector
__device__ float g_score0[BT_ * C_];     // partial score (h first half)
__device__ float g_score1[BT_ * C_];     // partial score (h second half)
__device__ float g_coef[BT_ * C_];       // softmax over T

__device__ __forceinline__ float tanh_fast(float x) {
    float y;
    asm("tanh.approx.f32 %0, %1;" : "=f"(y) : "f"(x));
    return y;
}

__device__ __forceinline__ void fma2(u64& d, u64 a, u64 b) {
    asm("fma.rn.f32x2 %0, %1, %2, %0;" : "+l"(d) : "l"(a), "l"(b));
}
__device__ __forceinline__ float unpk_sum(u64 v) {
    float lo, hi;
    asm("mov.b64 {%0,%1}, %2;" : "=f"(lo), "=f"(hi) : "l"(v));
    return lo + hi;
}

// ---------------- K1: veff = Wa @ W3, single kernel ----------------
// grid 32, block 256 = 32 h-lanes x 8 o-warps. Coalesced W3 reads.
__global__ void prep_kernel(const float* __restrict__ W3, const float* __restrict__ Wa) {
    __shared__ float red[8][33];
    int hl = threadIdx.x & 31;
    int og = threadIdx.x >> 5;      // 0..7
    int h = blockIdx.x * 32 + hl;
    float acc = 0.f;
#pragma unroll 8
    for (int o = og; o < H_; o += 8)
        acc += Wa[o] * W3[(size_t)o * H_ + h];
    red[og][hl] = acc;
    __syncthreads();
    if (og == 0) {
        float s = red[0][hl];
#pragma unroll
        for (int g = 1; g < 8; g++) s += red[g][hl];
        g_veff[h] = s;
    }
}

// ---------------- GEMM: C[M,N] = A[M,K] . B[N,K]^T ----------------
// 64x64 tile, 128 threads, 8m x 4n microtile, f32x2 k-paired accumulation.
__global__ void __launch_bounds__(128) gemm_nt2(const float* __restrict__ A,
                                                const float* __restrict__ B,
                                                float* __restrict__ C,
                                                int M, int N, int K, int Kc) {
    __shared__ float As2[8 * 128];   // [k2][m][2]
    __shared__ float Bs2[8 * 128];   // [k2][n][2]
    int tid = threadIdx.x;
    int m0 = blockIdx.x * 64;
    int n0 = blockIdx.y * 64;
    int k0g = blockIdx.z * Kc;
    int Kend = min(k0g + Kc, K);
    float* Cout = C + (size_t)blockIdx.z * M * N;

    int lr = tid >> 1;             // 0..63 tile row
    int lk = (tid & 1) * 8;        // k offset 0/8
    int k2b = lk >> 1;             // 0 or 4
    int gmA = min(m0 + lr, M - 1);
    const float* Ap = A + (size_t)gmA * K + lk;
    const float* Bp = B + (size_t)(n0 + lr) * K + lk;

    int tx = tid & 15;             // n = n0 + tx*4
    int ty = tid >> 4;             // m = m0 + ty*8

    u64 acc[8][4];
#pragma unroll
    for (int i = 0; i < 8; i++)
#pragma unroll
        for (int j = 0; j < 4; j++) acc[i][j] = 0ull;

    float4 a0, a1, b0, b1;
    {
        int kk = k0g;
        if (kk + 16 <= Kend) {
            a0 = *(const float4*)(Ap + kk); a1 = *(const float4*)(Ap + kk + 4);
            b0 = *(const float4*)(Bp + kk); b1 = *(const float4*)(Bp + kk + 4);
        } else {
            float t[8];
#pragma unroll
            for (int i = 0; i < 8; i++) t[i] = (kk + lk + i < Kend) ? Ap[kk + i] : 0.f;
            a0 = make_float4(t[0], t[1], t[2], t[3]); a1 = make_float4(t[4], t[5], t[6], t[7]);
#pragma unroll
            for (int i = 0; i < 8; i++) t[i] = (kk + lk + i < Kend) ? Bp[kk + i] : 0.f;
            b0 = make_float4(t[0], t[1], t[2], t[3]); b1 = make_float4(t[4], t[5], t[6], t[7]);
        }
    }

    for (int k0 = k0g; k0 < Kend; k0 += 16) {
        *(float2*)&As2[(k2b + 0) * 128 + lr * 2] = make_float2(a0.x, a0.y);
        *(float2*)&As2[(k2b + 1) * 128 + lr * 2] = make_float2(a0.z, a0.w);
        *(float2*)&As2[(k2b + 2) * 128 + lr * 2] = make_float2(a1.x, a1.y);
        *(float2*)&As2[(k2b + 3) * 128 + lr * 2] = make_float2(a1.z, a1.w);
        *(float2*)&Bs2[(k2b + 0) * 128 + lr * 2] = make_float2(b0.x, b0.y);
        *(float2*)&Bs2[(k2b + 1) * 128 + lr * 2] = make_float2(b0.z, b0.w);
        *(float2*)&Bs2[(k2b + 2) * 128 + lr * 2] = make_float2(b1.x, b1.y);
        *(float2*)&Bs2[(k2b + 3) * 128 + lr * 2] = make_float2(b1.z, b1.w);
        __syncthreads();

        float4 na0, na1, nb0, nb1;
        int kn = k0 + 16;
        bool more = kn < Kend;
        if (more) {
            if (kn + 16 <= Kend) {
                na0 = *(const float4*)(Ap + kn); na1 = *(const float4*)(Ap + kn + 4);
                nb0 = *(const float4*)(Bp + kn); nb1 = *(const float4*)(Bp + kn + 4);
            } else {
                float t[8];
#pragma unroll
                for (int i = 0; i < 8; i++) t[i] = (kn + lk + i < Kend) ? Ap[kn + i] : 0.f;
                na0 = make_float4(t[0], t[1], t[2], t[3]); na1 = make_float4(t[4], t[5], t[6], t[7]);
#pragma unroll
                for (int i = 0; i < 8; i++) t[i] = (kn + lk + i < Kend) ? Bp[kn + i] : 0.f;
                nb0 = make_float4(t[0], t[1], t[2], t[3]); nb1 = make_float4(t[4], t[5], t[6], t[7]);
            }
        }

#pragma unroll
        for (int k2 = 0; k2 < 8; k2++) {
            ulonglong2 A01 = *(const ulonglong2*)&As2[k2 * 128 + ty * 16];
            ulonglong2 A23 = *(const ulonglong2*)&As2[k2 * 128 + ty * 16 + 4];
            ulonglong2 A45 = *(const ulonglong2*)&As2[k2 * 128 + ty * 16 + 8];
            ulonglong2 A67 = *(const ulonglong2*)&As2[k2 * 128 + ty * 16 + 12];
            ulonglong2 B01 = *(const ulonglong2*)&Bs2[k2 * 128 + tx * 8];
            ulonglong2 B23 = *(const ulonglong2*)&Bs2[k2 * 128 + tx * 8 + 4];
            u64 am[8] = {A01.x, A01.y, A23.x, A23.y, A45.x, A45.y, A67.x, A67.y};
            u64 bn[4] = {B01.x, B01.y, B23.x, B23.y};
#pragma unroll
            for (int i = 0; i < 8; i++) {
                fma2(acc[i][0], am[i], bn[0]);
                fma2(acc[i][1], am[i], bn[1]);
                fma2(acc[i][2], am[i], bn[2]);
                fma2(acc[i][3], am[i], bn[3]);
            }
        }
        __syncthreads();
        if (more) { a0 = na0; a1 = na1; b0 = nb0; b1 = nb1; }
    }

#pragma unroll
    for (int i = 0; i < 8; i++) {
        int gm = m0 + ty * 8 + i;
        if (gm >= M) continue;
        float4 o;
        o.x = unpk_sum(acc[i][0]);
        o.y = unpk_sum(acc[i][1]);
        o.z = unpk_sum(acc[i][2]);
        o.w = unpk_sum(acc[i][3]);
        *(float4*)&Cout[(size_t)gm * N + n0 + tx * 4] = o;
    }
}

// ---------------- K4: partial score over one H half ----------------
// CTA tile 16 bt x 64 c, 256 threads, 2bt x 2c per thread. grid (16, 9, 2).
// Fuses the split-K merge of fc_1 partials into the a-tile load.
// w tile stored c-major [c][68] -> 2 LDS.128 per hh (conflict-free, stride 17 x 16B).
__global__ void __launch_bounds__(256, 2) score_kernel() {
    __shared__ float a_s[16][64];
    __shared__ float w_s[64][68];
    __shared__ float v_s[64];
    int tid  = threadIdx.x;
    int lane = tid & 31;
    int warp = tid >> 5;            // 0..7
    int bt0  = blockIdx.x * 16;
    int c0   = blockIdx.y * 64;
    int hb0  = blockIdx.z * (H_ / 2);
    float* out = blockIdx.z ? g_score1 : g_score0;
    float s00 = 0.f, s01 = 0.f, s10 = 0.f, s11 = 0.f;

    for (int h0 = hb0; h0 < hb0 + H_ / 2; h0 += 64) {
        // a tile with fused split-K merge
        {
            int r = tid >> 4;              // 0..15
            int c4 = (tid & 15) * 4;       // 0..60
            size_t ai = (size_t)(bt0 + r) * H_ + h0 + c4;
            float4 x = *(const float4*)&g_apart[ai];
            float4 y = *(const float4*)&g_apart[(size_t)BT_ * H_ + ai];
            x.x += y.x; x.y += y.y; x.z += y.z; x.w += y.w;
            *(float4*)&a_s[r][c4] = x;
        }
        if (tid < 64) v_s[tid] = g_veff[h0 + tid];
        // w tile, c-major: thread -> c = tid>>2 (0..63), q = tid&3 -> 4 float4
        {
            int c = tid >> 2, q = tid & 3;
            int cg = c0 + c;
            bool ok = cg < C_;
            const float4* wrow = (const float4*)(g_w + (size_t)(ok ? cg : C_ - 1) * H_ + h0);
            float4 z = make_float4(0.f, 0.f, 0.f, 0.f);
#pragma unroll
            for (int i = 0; i < 4; i++)
                *(float4*)&w_s[c][q * 16 + i * 4] = ok ? wrow[q * 4 + i] : z;
        }
        __syncthreads();

        const float4* a4r0 = (const float4*)a_s[warp];
        const float4* a4r1 = (const float4*)a_s[warp + 8];
        const float4* v4   = (const float4*)v_s;
#pragma unroll
        for (int hh = 0; hh < 16; hh++) {
            float4 av0 = a4r0[hh];
            float4 av1 = a4r1[hh];
            float4 vv  = v4[hh];
            float4 wA = *(const float4*)&w_s[lane][hh * 4];
            float4 wB = *(const float4*)&w_s[lane + 32][hh * 4];
            s00 = fmaf(tanh_fast(av0.x * wA.x), vv.x, s00);
            s01 = fmaf(tanh_fast(av0.x * wB.x), vv.x, s01);
            s10 = fmaf(tanh_fast(av1.x * wA.x), vv.x, s10);
            s11 = fmaf(tanh_fast(av1.x * wB.x), vv.x, s11);
            s00 = fmaf(tanh_fast(av0.y * wA.y), vv.y, s00);
            s01 = fmaf(tanh_fast(av0.y * wB.y), vv.y, s01);
            s10 = fmaf(tanh_fast(av1.y * wA.y), vv.y, s10);
            s11 = fmaf(tanh_fast(av1.y * wB.y), vv.y, s11);
            s00 = fmaf(tanh_fast(av0.z * wA.z), vv.z, s00);
            s01 = fmaf(tanh_fast(av0.z * wB.z), vv.z, s01);
            s10 = fmaf(tanh_fast(av1.z * wA.z), vv.z, s10);
            s11 = fmaf(tanh_fast(av1.z * wB.z), vv.z, s11);
            s00 = fmaf(tanh_fast(av0.w * wA.w), vv.w, s00);
            s01 = fmaf(tanh_fast(av0.w * wB.w), vv.w, s01);
            s10 = fmaf(tanh_fast(av1.w * wA.w), vv.w, s10);
            s11 = fmaf(tanh_fast(av1.w * wB.w), vv.w, s11);
        }
        __syncthreads();
    }
    int ca = c0 + lane, cb = c0 + lane + 32;
    int base0 = (bt0 + warp) * C_;
    int base1 = (bt0 + warp + 8) * C_;
    if (ca < C_) {
        out[base0 + ca] = s00;
        out[base1 + ca] = s10;
    }
    if (cb < C_) {
        out[base0 + cb] = s01;
        out[base1 + cb] = s11;
    }
}

// ---------------- K5: softmax over T per (b,c), coalesced ----------------
// grid (ceil(C/32), B), block 256 = 32 c-lanes x 8 t-groups; all GMEM 128B coalesced.
__global__ void softmax_kernel() {
    __shared__ float redm[8][33], reds[8][33];
    int cl = threadIdx.x & 31;
    int tg = threadIdx.x >> 5;     // 0..7
    int b  = blockIdx.y;
    int c  = blockIdx.x * 32 + cl;
    bool ok = c < C_;
    int cc = ok ? c : C_ - 1;

    float v[16];
    float m = -1e30f;
#pragma unroll
    for (int i = 0; i < 16; i++) {
        int idx = (b * T_ + tg + i * 8) * C_ + cc;
        v[i] = g_score0[idx] + g_score1[idx];
        m = fmaxf(m, v[i]);
    }
    redm[tg][cl] = m;
    __syncthreads();
    m = redm[0][cl];
#pragma unroll
    for (int g = 1; g < 8; g++) m = fmaxf(m, redm[g][cl]);

    float s = 0.f;
#pragma unroll
    for (int i = 0; i < 16; i++) {
        v[i] = __expf(v[i] - m);
        s += v[i];
    }
    reds[tg][cl] = s;
    __syncthreads();
    s = reds[0][cl];
#pragma unroll
    for (int g = 1; g < 8; g++) s += reds[g][cl];
    float inv = 1.f / s;
    if (ok) {
#pragma unroll
        for (int i = 0; i < 16; i++)
            g_coef[(b * T_ + tg + i * 8) * C_ + c] = v[i] * inv;
    }
}

// ---------------- K6: out[b,c,d] = sum_t coef[b,t,c] * audio[b,t,d] ----------------
__global__ void __launch_bounds__(128) pool2(const float* __restrict__ audio,
                                             float* __restrict__ out) {
    __shared__ float As2[8 * 128];   // [k2][c][2]
    __shared__ float Bs2[8 * 128];   // [k2][d][2]
    int b = blockIdx.z;
    const float* coefb = g_coef + (size_t)b * T_ * C_;
    const float* audb  = audio + (size_t)b * T_ * DA_;
    float* Cout = out + (size_t)b * C_ * DA_;
    int tid = threadIdx.x;
    int m0 = blockIdx.x * 64;
    int n0 = blockIdx.y * 64;

    int lm  = tid & 63;
    int lkg = tid >> 6;
    int gm  = min(m0 + lm, C_ - 1);

    int tx = tid & 15, ty = tid >> 4;

    u64 acc[8][4];
#pragma unroll
    for (int i = 0; i < 8; i++)
#pragma unroll
        for (int j = 0; j < 4; j++) acc[i][j] = 0ull;

    float2 pa[4], pb[4];
#pragma unroll
    for (int i = 0; i < 4; i++) {
        int ke = lkg * 8 + 2 * i;
        pa[i] = make_float2(coefb[(size_t)ke * C_ + gm], coefb[(size_t)(ke + 1) * C_ + gm]);
        pb[i] = make_float2(audb[(size_t)ke * DA_ + n0 + lm], audb[(size_t)(ke + 1) * DA_ + n0 + lm]);
    }

    for (int k0 = 0; k0 < T_; k0 += 16) {
#pragma unroll
        for (int i = 0; i < 4; i++) {
            *(float2*)&As2[(lkg * 4 + i) * 128 + lm * 2] = pa[i];
            *(float2*)&Bs2[(lkg * 4 + i) * 128 + lm * 2] = pb[i];
        }
        __syncthreads();
        int kn = k0 + 16;
        if (kn < T_) {
#pragma unroll
            for (int i = 0; i < 4; i++) {
                int ke = kn + lkg * 8 + 2 * i;
                pa[i] = make_float2(coefb[(size_t)ke * C_ + gm], coefb[(size_t)(ke + 1) * C_ + gm]);
                pb[i] = make_float2(audb[(size_t)ke * DA_ + n0 + lm], audb[(size_t)(ke + 1) * DA_ + n0 + lm]);
            }
        }
#pragma unroll
        for (int k2 = 0; k2 < 8; k2++) {
            ulonglong2 A01 = *(const ulonglong2*)&As2[k2 * 128 + ty * 16];
            ulonglong2 A23 = *(const ulonglong2*)&As2[k2 * 128 + ty * 16 + 4];
            ulonglong2 A45 = *(const ulonglong2*)&As2[k2 * 128 + ty * 16 + 8];
            ulonglong2 A67 = *(const ulonglong2*)&As2[k2 * 128 + ty * 16 + 12];
            ulonglong2 B01 = *(const ulonglong2*)&Bs2[k2 * 128 + tx * 8];
            ulonglong2 B23 = *(const ulonglong2*)&Bs2[k2 * 128 + tx * 8 + 4];
            u64 am[8] = {A01.x, A01.y, A23.x, A23.y, A45.x, A45.y, A67.x, A67.y};
            u64 bn[4] = {B01.x, B01.y, B23.x, B23.y};
#pragma unroll
            for (int i = 0; i < 8; i++) {
                fma2(acc[i][0], am[i], bn[0]);
                fma2(acc[i][1], am[i], bn[1]);
                fma2(acc[i][2], am[i], bn[2]);
                fma2(acc[i][3], am[i], bn[3]);
            }
        }
        __syncthreads();
    }

#pragma unroll
    for (int i = 0; i < 8; i++) {
        int gm2 = m0 + ty * 8 + i;
        if (gm2 >= C_) continue;
        float4 o;
        o.x = unpk_sum(acc[i][0]);
        o.y = unpk_sum(acc[i][1]);
        o.z = unpk_sum(acc[i][2]);
        o.w = unpk_sum(acc[i][3]);
        *(float4*)&Cout[(size_t)gm2 * DA_ + n0 + tx * 4] = o;
    }
}

// ---------------- launch ----------------
extern "C" void kernel_launch(void* const* d_in, const int* in_sizes, int n_in,
                              void* d_out, int out_size) {
    const float* audio = (const float*)d_in[0];   // [B,T,DA]
    const float* word  = (const float*)d_in[1];   // [C,DW]
    const float* W1    = (const float*)d_in[2];   // [H,DA]
    const float* W2    = (const float*)d_in[3];   // [H,DW]
    const float* W3    = (const float*)d_in[4];   // [H,H]
    const float* Wa    = (const float*)d_in[6];   // [1,H]
    float* out = (float*)d_out;                   // [B,C,DA]
    (void)in_sizes; (void)n_in; (void)out_size;

    void *papart = nullptr, *pw = nullptr;
    cudaGetSymbolAddress(&papart, g_apart);
    cudaGetSymbolAddress(&pw, g_w);

    // (1) veff = Wa @ W3
    prep_kernel<<<32, 256>>>(W3, Wa);
    // (2) a partials = audio @ W1^T, split-K 2 (merge fused into score)
    gemm_nt2<<<dim3(BT_ / 64, H_ / 64, 2), 128>>>(audio, W1, (float*)papart, BT_, H_, DA_, DA_ / 2);
    // (3) w = word @ W2^T
    gemm_nt2<<<dim3((C_ + 63) / 64, H_ / 64, 1), 128>>>(word, W2, (float*)pw, C_, H_, DW_, DW_);
    // (4) fused tanh-dot score (PROFILED SLOT)
    score_kernel<<<dim3(BT_ / 16, (C_ + 63) / 64, 2), 256>>>();
    // (5) softmax over T, coalesced
    softmax_kernel<<<dim3((C_ + 31) / 32, B_), 256>>>();
    // (6) softmax-weighted pooling
    pool2<<<dim3((C_ + 63) / 64, DA_ / 64, B_), 128>>>(audio, out);
}

// round 6
// speedup vs baseline: 1.7532x; 1.1691x over previous
#include <cuda_runtime.h>
#include <cuda_bf16.h>

// Problem constants
#define B_   2
#define T_   128
#define C_   527
#define DA_  1024
#define DW_  300
#define H_   1024
#define BT_  (B_ * T_)   // 256

typedef unsigned long long u64;

// ---------------- device scratch ----------------
__device__ float g_apart[2 * BT_ * H_];  // split-K partials for fc_1
__device__ float g_w[C_ * H_];           // fc_2 output [527,1024]
__device__ float g_vpart[4 * H_];        // veff partials (4 o-chunks)
__device__ float g_score0[BT_ * C_];     // partial score (h first half)
__device__ float g_score1[BT_ * C_];     // partial score (h second half)
__device__ float g_coef[BT_ * C_];       // softmax over T

__device__ __forceinline__ float tanh_fast(float x) {
    float y;
    asm("tanh.approx.f32 %0, %1;" : "=f"(y) : "f"(x));
    return y;
}
__device__ __forceinline__ void fma2(u64& d, u64 a, u64 b) {
    asm("fma.rn.f32x2 %0, %1, %2, %0;" : "+l"(d) : "l"(a), "l"(b));
}
__device__ __forceinline__ float unpk_sum(u64 v) {
    float lo, hi;
    asm("mov.b64 {%0,%1}, %2;" : "=f"(lo), "=f"(hi) : "l"(v));
    return lo + hi;
}
// acc += tanh(a*w) * v, packed over an h-pair
__device__ __forceinline__ void tvstep(u64& acc, u64 a, u64 w, u64 v) {
    u64 x;
    asm("mul.rn.f32x2 %0, %1, %2;" : "=l"(x) : "l"(a), "l"(w));
    float xl, xh;
    asm("mov.b64 {%0,%1}, %2;" : "=f"(xl), "=f"(xh) : "l"(x));
    float tl = tanh_fast(xl), th = tanh_fast(xh);
    u64 t;
    asm("mov.b64 %0, {%1,%2};" : "=l"(t) : "f"(tl), "f"(th));
    asm("fma.rn.f32x2 %0, %1, %2, %0;" : "+l"(acc) : "l"(t), "l"(v));
}

// ---------------- GEMM body: C[M,N] = A[M,K] . B[N,K]^T ----------------
// 64x64 tile, 128 threads, 8m x 4n microtile, f32x2 k-paired accumulation.
__device__ __forceinline__ void gemm_body(const float* __restrict__ A,
                                          const float* __restrict__ B,
                                          float* __restrict__ C,
                                          int M, int N, int K, int Kc,
                                          int bx, int by, int bz,
                                          int tid, float* As2, float* Bs2) {
    int m0 = bx * 64;
    int n0 = by * 64;
    int k0g = bz * Kc;
    int Kend = min(k0g + Kc, K);
    float* Cout = C + (size_t)bz * M * N;

    int lr = tid >> 1;
    int lk = (tid & 1) * 8;
    int k2b = lk >> 1;
    int gmA = min(m0 + lr, M - 1);
    const float* Ap = A + (size_t)gmA * K + lk;
    const float* Bp = B + (size_t)(n0 + lr) * K + lk;

    int tx = tid & 15;
    int ty = tid >> 4;

    u64 acc[8][4];
#pragma unroll
    for (int i = 0; i < 8; i++)
#pragma unroll
        for (int j = 0; j < 4; j++) acc[i][j] = 0ull;

    float4 a0, a1, b0, b1;
    {
        int kk = k0g;
        if (kk + 16 <= Kend) {
            a0 = *(const float4*)(Ap + kk); a1 = *(const float4*)(Ap + kk + 4);
            b0 = *(const float4*)(Bp + kk); b1 = *(const float4*)(Bp + kk + 4);
        } else {
            float t[8];
#pragma unroll
            for (int i = 0; i < 8; i++) t[i] = (kk + lk + i < Kend) ? Ap[kk + i] : 0.f;
            a0 = make_float4(t[0], t[1], t[2], t[3]); a1 = make_float4(t[4], t[5], t[6], t[7]);
#pragma unroll
            for (int i = 0; i < 8; i++) t[i] = (kk + lk + i < Kend) ? Bp[kk + i] : 0.f;
            b0 = make_float4(t[0], t[1], t[2], t[3]); b1 = make_float4(t[4], t[5], t[6], t[7]);
        }
    }

    for (int k0 = k0g; k0 < Kend; k0 += 16) {
        *(float2*)&As2[(k2b + 0) * 128 + lr * 2] = make_float2(a0.x, a0.y);
        *(float2*)&As2[(k2b + 1) * 128 + lr * 2] = make_float2(a0.z, a0.w);
        *(float2*)&As2[(k2b + 2) * 128 + lr * 2] = make_float2(a1.x, a1.y);
        *(float2*)&As2[(k2b + 3) * 128 + lr * 2] = make_float2(a1.z, a1.w);
        *(float2*)&Bs2[(k2b + 0) * 128 + lr * 2] = make_float2(b0.x, b0.y);
        *(float2*)&Bs2[(k2b + 1) * 128 + lr * 2] = make_float2(b0.z, b0.w);
        *(float2*)&Bs2[(k2b + 2) * 128 + lr * 2] = make_float2(b1.x, b1.y);
        *(float2*)&Bs2[(k2b + 3) * 128 + lr * 2] = make_float2(b1.z, b1.w);
        __syncthreads();

        float4 na0, na1, nb0, nb1;
        int kn = k0 + 16;
        bool more = kn < Kend;
        if (more) {
            if (kn + 16 <= Kend) {
                na0 = *(const float4*)(Ap + kn); na1 = *(const float4*)(Ap + kn + 4);
                nb0 = *(const float4*)(Bp + kn); nb1 = *(const float4*)(Bp + kn + 4);
            } else {
                float t[8];
#pragma unroll
                for (int i = 0; i < 8; i++) t[i] = (kn + lk + i < Kend) ? Ap[kn + i] : 0.f;
                na0 = make_float4(t[0], t[1], t[2], t[3]); na1 = make_float4(t[4], t[5], t[6], t[7]);
#pragma unroll
                for (int i = 0; i < 8; i++) t[i] = (kn + lk + i < Kend) ? Bp[kn + i] : 0.f;
                nb0 = make_float4(t[0], t[1], t[2], t[3]); nb1 = make_float4(t[4], t[5], t[6], t[7]);
            }
        }

#pragma unroll
        for (int k2 = 0; k2 < 8; k2++) {
            ulonglong2 A01 = *(const ulonglong2*)&As2[k2 * 128 + ty * 16];
            ulonglong2 A23 = *(const ulonglong2*)&As2[k2 * 128 + ty * 16 + 4];
            ulonglong2 A45 = *(const ulonglong2*)&As2[k2 * 128 + ty * 16 + 8];
            ulonglong2 A67 = *(const ulonglong2*)&As2[k2 * 128 + ty * 16 + 12];
            ulonglong2 B01 = *(const ulonglong2*)&Bs2[k2 * 128 + tx * 8];
            ulonglong2 B23 = *(const ulonglong2*)&Bs2[k2 * 128 + tx * 8 + 4];
            u64 am[8] = {A01.x, A01.y, A23.x, A23.y, A45.x, A45.y, A67.x, A67.y};
            u64 bn[4] = {B01.x, B01.y, B23.x, B23.y};
#pragma unroll
            for (int i = 0; i < 8; i++) {
                fma2(acc[i][0], am[i], bn[0]);
                fma2(acc[i][1], am[i], bn[1]);
                fma2(acc[i][2], am[i], bn[2]);
                fma2(acc[i][3], am[i], bn[3]);
            }
        }
        __syncthreads();
        if (more) { a0 = na0; a1 = na1; b0 = nb0; b1 = nb1; }
    }

#pragma unroll
    for (int i = 0; i < 8; i++) {
        int gm = m0 + ty * 8 + i;
        if (gm >= M) continue;
        float4 o;
        o.x = unpk_sum(acc[i][0]);
        o.y = unpk_sum(acc[i][1]);
        o.z = unpk_sum(acc[i][2]);
        o.w = unpk_sum(acc[i][3]);
        *(float4*)&Cout[(size_t)gm * N + n0 + tx * 4] = o;
    }
}

// ---------------- K1 fat kernel: K2 gemm + K3 gemm + veff prep ----------------
// blocks [0,128): fc_1 split-K gemm; [128,272): fc_2 gemm; [272,400): veff partials.
__global__ void __launch_bounds__(128) fat_kernel(const float* __restrict__ audio,
                                                  const float* __restrict__ word,
                                                  const float* __restrict__ W1,
                                                  const float* __restrict__ W2,
                                                  const float* __restrict__ W3,
                                                  const float* __restrict__ Wa) {
    __shared__ __align__(16) float As2[8 * 128];
    __shared__ __align__(16) float Bs2[8 * 128];
    __shared__ float red[4][33];
    int ib = blockIdx.x;
    int tid = threadIdx.x;
    void* papart; void* pwv;
    if (ib < 128) {
        // K2: a partials = audio @ W1^T, split-K 2
        asm("mov.u64 %0, g_apart;" : "=l"(papart));
        gemm_body(audio, W1, (float*)&g_apart[0], BT_, H_, DA_, DA_ / 2,
                  ib & 3, (ib >> 2) & 15, ib >> 6, tid, As2, Bs2);
        (void)papart; (void)pwv;
    } else if (ib < 272) {
        int j = ib - 128;   // 0..143 -> (x 0..8, y 0..15)
        gemm_body(word, W2, (float*)&g_w[0], C_, H_, DW_, DW_,
                  j % 9, j / 9, 0, tid, As2, Bs2);
    } else {
        // veff partials: p = 0..127; hb = p&31 (32 h), ob = p>>5 (256 o rows)
        int p = ib - 272;
        int hb = p & 31, ob = p >> 5;
        int hl = tid & 31;
        int og = tid >> 5;          // 0..3
        int h = hb * 32 + hl;
        float acc = 0.f;
#pragma unroll 8
        for (int o = ob * 256 + og; o < ob * 256 + 256; o += 4)
            acc += Wa[o] * W3[(size_t)o * H_ + h];
        red[og][hl] = acc;
        __syncthreads();
        if (og == 0)
            g_vpart[ob * H_ + h] = red[0][hl] + red[1][hl] + red[2][hl] + red[3][hl];
    }
}

// ---------------- K4: partial score over one H half, f32x2 packed ----------------
// CTA tile 16 bt x 64 c, 256 threads, 2bt x 2c per thread. grid (16, 9, 2).
__global__ void __launch_bounds__(256, 2) score_kernel() {
    __shared__ __align__(16) float a_s[16][64];
    __shared__ __align__(16) float w_s[64][68];
    __shared__ __align__(16) float v_s[64];
    int tid  = threadIdx.x;
    int lane = tid & 31;
    int warp = tid >> 5;            // 0..7
    int bt0  = blockIdx.x * 16;
    int c0   = blockIdx.y * 64;
    int hb0  = blockIdx.z * (H_ / 2);
    float* out = blockIdx.z ? g_score1 : g_score0;
    u64 p00 = 0ull, p01 = 0ull, p10 = 0ull, p11 = 0ull;

    for (int h0 = hb0; h0 < hb0 + H_ / 2; h0 += 64) {
        // a tile with fused split-K merge
        {
            int r = tid >> 4;              // 0..15
            int c4 = (tid & 15) * 4;       // 0..60
            size_t ai = (size_t)(bt0 + r) * H_ + h0 + c4;
            float4 x = *(const float4*)&g_apart[ai];
            float4 y = *(const float4*)&g_apart[(size_t)BT_ * H_ + ai];
            x.x += y.x; x.y += y.y; x.z += y.z; x.w += y.w;
            *(float4*)&a_s[r][c4] = x;
        }
        // v tile: sum the 4 o-chunk partials
        if (tid < 64) {
            int h = h0 + tid;
            v_s[tid] = g_vpart[h] + g_vpart[H_ + h] + g_vpart[2 * H_ + h] + g_vpart[3 * H_ + h];
        }
        // w tile, c-major
        {
            int c = tid >> 2, q = tid & 3;
            int cg = c0 + c;
            bool ok = cg < C_;
            const float4* wrow = (const float4*)(g_w + (size_t)(ok ? cg : C_ - 1) * H_ + h0);
            float4 z = make_float4(0.f, 0.f, 0.f, 0.f);
#pragma unroll
            for (int i = 0; i < 4; i++)
                *(float4*)&w_s[c][q * 16 + i * 4] = ok ? wrow[q * 4 + i] : z;
        }
        __syncthreads();

#pragma unroll
        for (int hh = 0; hh < 16; hh++) {
            ulonglong2 av0 = *(const ulonglong2*)&a_s[warp][hh * 4];
            ulonglong2 av1 = *(const ulonglong2*)&a_s[warp + 8][hh * 4];
            ulonglong2 wA  = *(const ulonglong2*)&w_s[lane][hh * 4];
            ulonglong2 wB  = *(const ulonglong2*)&w_s[lane + 32][hh * 4];
            ulonglong2 vv  = *(const ulonglong2*)&v_s[hh * 4];
            tvstep(p00, av0.x, wA.x, vv.x);
            tvstep(p01, av0.x, wB.x, vv.x);
            tvstep(p10, av1.x, wA.x, vv.x);
            tvstep(p11, av1.x, wB.x, vv.x);
            tvstep(p00, av0.y, wA.y, vv.y);
            tvstep(p01, av0.y, wB.y, vv.y);
            tvstep(p10, av1.y, wA.y, vv.y);
            tvstep(p11, av1.y, wB.y, vv.y);
        }
        __syncthreads();
    }
    float s00 = unpk_sum(p00), s01 = unpk_sum(p01);
    float s10 = unpk_sum(p10), s11 = unpk_sum(p11);
    int ca = c0 + lane, cb = c0 + lane + 32;
    int base0 = (bt0 + warp) * C_;
    int base1 = (bt0 + warp + 8) * C_;
    if (ca < C_) {
        out[base0 + ca] = s00;
        out[base1 + ca] = s10;
    }
    if (cb < C_) {
        out[base0 + cb] = s01;
        out[base1 + cb] = s11;
    }
}

// ---------------- K5: softmax over T per (b,c), coalesced ----------------
__global__ void softmax_kernel() {
    __shared__ float redm[8][33], reds[8][33];
    int cl = threadIdx.x & 31;
    int tg = threadIdx.x >> 5;     // 0..7
    int b  = blockIdx.y;
    int c  = blockIdx.x * 32 + cl;
    bool ok = c < C_;
    int cc = ok ? c : C_ - 1;

    float v[16];
    float m = -1e30f;
#pragma unroll
    for (int i = 0; i < 16; i++) {
        int idx = (b * T_ + tg + i * 8) * C_ + cc;
        v[i] = g_score0[idx] + g_score1[idx];
        m = fmaxf(m, v[i]);
    }
    redm[tg][cl] = m;
    __syncthreads();
    m = redm[0][cl];
#pragma unroll
    for (int g = 1; g < 8; g++) m = fmaxf(m, redm[g][cl]);

    float s = 0.f;
#pragma unroll
    for (int i = 0; i < 16; i++) {
        v[i] = __expf(v[i] - m);
        s += v[i];
    }
    reds[tg][cl] = s;
    __syncthreads();
    s = reds[0][cl];
#pragma unroll
    for (int g = 1; g < 8; g++) s += reds[g][cl];
    float inv = 1.f / s;
    if (ok) {
#pragma unroll
        for (int i = 0; i < 16; i++)
            g_coef[(b * T_ + tg + i * 8) * C_ + c] = v[i] * inv;
    }
}

// ---------------- K6: out[b,c,d] = sum_t coef[b,t,c] * audio[b,t,d] ----------------
__global__ void __launch_bounds__(128) pool2(const float* __restrict__ audio,
                                             float* __restrict__ out) {
    __shared__ __align__(16) float As2[8 * 128];
    __shared__ __align__(16) float Bs2[8 * 128];
    int b = blockIdx.z;
    const float* coefb = g_coef + (size_t)b * T_ * C_;
    const float* audb  = audio + (size_t)b * T_ * DA_;
    float* Cout = out + (size_t)b * C_ * DA_;
    int tid = threadIdx.x;
    int m0 = blockIdx.x * 64;
    int n0 = blockIdx.y * 64;

    int lm  = tid & 63;
    int lkg = tid >> 6;
    int gm  = min(m0 + lm, C_ - 1);

    int tx = tid & 15, ty = tid >> 4;

    u64 acc[8][4];
#pragma unroll
    for (int i = 0; i < 8; i++)
#pragma unroll
        for (int j = 0; j < 4; j++) acc[i][j] = 0ull;

    float2 pa[4], pb[4];
#pragma unroll
    for (int i = 0; i < 4; i++) {
        int ke = lkg * 8 + 2 * i;
        pa[i] = make_float2(coefb[(size_t)ke * C_ + gm], coefb[(size_t)(ke + 1) * C_ + gm]);
        pb[i] = make_float2(audb[(size_t)ke * DA_ + n0 + lm], audb[(size_t)(ke + 1) * DA_ + n0 + lm]);
    }

    for (int k0 = 0; k0 < T_; k0 += 16) {
#pragma unroll
        for (int i = 0; i < 4; i++) {
            *(float2*)&As2[(lkg * 4 + i) * 128 + lm * 2] = pa[i];
            *(float2*)&Bs2[(lkg * 4 + i) * 128 + lm * 2] = pb[i];
        }
        __syncthreads();
        int kn = k0 + 16;
        if (kn < T_) {
#pragma unroll
            for (int i = 0; i < 4; i++) {
                int ke = kn + lkg * 8 + 2 * i;
                pa[i] = make_float2(coefb[(size_t)ke * C_ + gm], coefb[(size_t)(ke + 1) * C_ + gm]);
                pb[i] = make_float2(audb[(size_t)ke * DA_ + n0 + lm], audb[(size_t)(ke + 1) * DA_ + n0 + lm]);
            }
        }
#pragma unroll
        for (int k2 = 0; k2 < 8; k2++) {
            ulonglong2 A01 = *(const ulonglong2*)&As2[k2 * 128 + ty * 16];
            ulonglong2 A23 = *(const ulonglong2*)&As2[k2 * 128 + ty * 16 + 4];
            ulonglong2 A45 = *(const ulonglong2*)&As2[k2 * 128 + ty * 16 + 8];
            ulonglong2 A67 = *(const ulonglong2*)&As2[k2 * 128 + ty * 16 + 12];
            ulonglong2 B01 = *(const ulonglong2*)&Bs2[k2 * 128 + tx * 8];
            ulonglong2 B23 = *(const ulonglong2*)&Bs2[k2 * 128 + tx * 8 + 4];
            u64 am[8] = {A01.x, A01.y, A23.x, A23.y, A45.x, A45.y, A67.x, A67.y};
            u64 bn[4] = {B01.x, B01.y, B23.x, B23.y};
#pragma unroll
            for (int i = 0; i < 8; i++) {
                fma2(acc[i][0], am[i], bn[0]);
                fma2(acc[i][1], am[i], bn[1]);
                fma2(acc[i][2], am[i], bn[2]);
                fma2(acc[i][3], am[i], bn[3]);
            }
        }
        __syncthreads();
    }

#pragma unroll
    for (int i = 0; i < 8; i++) {
        int gm2 = m0 + ty * 8 + i;
        if (gm2 >= C_) continue;
        float4 o;
        o.x = unpk_sum(acc[i][0]);
        o.y = unpk_sum(acc[i][1]);
        o.z = unpk_sum(acc[i][2]);
        o.w = unpk_sum(acc[i][3]);
        *(float4*)&Cout[(size_t)gm2 * DA_ + n0 + tx * 4] = o;
    }
}

// ---------------- launch ----------------
extern "C" void kernel_launch(void* const* d_in, const int* in_sizes, int n_in,
                              void* d_out, int out_size) {
    const float* audio = (const float*)d_in[0];   // [B,T,DA]
    const float* word  = (const float*)d_in[1];   // [C,DW]
    const float* W1    = (const float*)d_in[2];   // [H,DA]
    const float* W2    = (const float*)d_in[3];   // [H,DW]
    const float* W3    = (const float*)d_in[4];   // [H,H]
    const float* Wa    = (const float*)d_in[6];   // [1,H]
    float* out = (float*)d_out;                   // [B,C,DA]
    (void)in_sizes; (void)n_in; (void)out_size;

    // (1) fused: fc_1 gemm (split-K) + fc_2 gemm + veff prep
    fat_kernel<<<400, 128>>>(audio, word, W1, W2, W3, Wa);
    // (2) fused tanh-dot score, f32x2 packed
    score_kernel<<<dim3(BT_ / 16, (C_ + 63) / 64, 2), 256>>>();
    // (3) softmax over T, coalesced
    softmax_kernel<<<dim3((C_ + 31) / 32, B_), 256>>>();
    // (4) softmax-weighted pooling (PROFILED SLOT)
    pool2<<<dim3((C_ + 63) / 64, DA_ / 64, B_), 128>>>(audio, out);
}